// round 2
// baseline (speedup 1.0000x reference)
#include <cuda_runtime.h>

#define N_USERC 100000
#define N_ITEMC 50000
#define NE      1600000
#define DU      128
#define DI      64
#define HH      256

// ---------------- device scratch (no runtime allocation allowed) ----------------
__device__ int g_cnt_item[N_ITEMC];
__device__ int g_cnt_user[N_USERC];
__device__ int g_cur_item[N_ITEMC];
__device__ int g_cur_user[N_USERC];
__device__ int g_rs_item[N_ITEMC + 1];
__device__ int g_rs_user[N_USERC + 1];
__device__ int g_col_ui[NE];   // per item-dst: list of user srcs
__device__ int g_col_iu[NE];   // per user-dst: list of item srcs

__device__ float g_agg_item[(size_t)N_ITEMC * DU];   // mean of x_user per item
__device__ float g_agg_user[(size_t)N_USERC * DI];   // mean of x_item per user
__device__ float g_h_item[(size_t)N_ITEMC * HH];
__device__ float g_h_user[(size_t)N_USERC * HH];
__device__ float g_aggH_item[(size_t)N_ITEMC * HH];  // mean of h_user per item
__device__ float g_aggH_user[(size_t)N_USERC * HH];  // mean of h_item per user

// ---------------- CSR build ----------------
__global__ void count_kernel(const int* __restrict__ ui_dst, const int* __restrict__ iu_dst) {
    int i = blockIdx.x * blockDim.x + threadIdx.x;
    if (i < NE) {
        atomicAdd(&g_cnt_item[ui_dst[i]], 1);
        atomicAdd(&g_cnt_user[iu_dst[i]], 1);
    }
}

// Exclusive scan over degree arrays; block 0 -> items, block 1 -> users.
__global__ void scan_kernel() {
    const int* cnt = (blockIdx.x == 0) ? g_cnt_item : g_cnt_user;
    int*       rs  = (blockIdx.x == 0) ? g_rs_item  : g_rs_user;
    const int  n   = (blockIdx.x == 0) ? N_ITEMC    : N_USERC;

    __shared__ int sm[1024];
    __shared__ int running;
    if (threadIdx.x == 0) running = 0;
    __syncthreads();

    for (int base = 0; base < n; base += 1024) {
        int i = base + threadIdx.x;
        int v = (i < n) ? cnt[i] : 0;
        sm[threadIdx.x] = v;
        __syncthreads();
        // Hillis–Steele inclusive scan
        for (int off = 1; off < 1024; off <<= 1) {
            int t = (threadIdx.x >= (unsigned)off) ? sm[threadIdx.x - off] : 0;
            __syncthreads();
            sm[threadIdx.x] += t;
            __syncthreads();
        }
        if (i < n) rs[i] = running + sm[threadIdx.x] - v;   // exclusive
        int tot = sm[1023];
        __syncthreads();
        if (threadIdx.x == 0) running += tot;
        __syncthreads();
    }
    if (threadIdx.x == 0) rs[n] = running;
}

__global__ void fill_kernel(const int* __restrict__ ui_src, const int* __restrict__ ui_dst,
                            const int* __restrict__ iu_src, const int* __restrict__ iu_dst) {
    int i = blockIdx.x * blockDim.x + threadIdx.x;
    if (i >= NE) return;
    {
        int d = ui_dst[i];
        int p = atomicAdd(&g_cur_item[d], 1);
        g_col_ui[g_rs_item[d] + p] = ui_src[i];
    }
    {
        int d = iu_dst[i];
        int p = atomicAdd(&g_cur_user[d], 1);
        g_col_iu[g_rs_user[d] + p] = iu_src[i];
    }
}

// ---------------- gather-based segment mean ----------------
// One warp per destination row; F = NV*128 floats per row, float4 per lane per NV.
template <int NV>
__global__ __launch_bounds__(256) void agg_mean_v4(const float* __restrict__ X,
                                                   const int* __restrict__ rs,
                                                   const int* __restrict__ col,
                                                   float* __restrict__ out, int ndst) {
    int w = blockIdx.x * 8 + (threadIdx.x >> 5);
    int lane = threadIdx.x & 31;
    if (w >= ndst) return;
    int s = rs[w], e = rs[w + 1];
    constexpr int F = NV * 128;

    float4 acc0[NV], acc1[NV];
#pragma unroll
    for (int v = 0; v < NV; v++) {
        acc0[v] = make_float4(0.f, 0.f, 0.f, 0.f);
        acc1[v] = make_float4(0.f, 0.f, 0.f, 0.f);
    }
    int j = s;
    for (; j + 1 < e; j += 2) {
        const float4* r0 = (const float4*)(X + (size_t)col[j] * F);
        const float4* r1 = (const float4*)(X + (size_t)col[j + 1] * F);
#pragma unroll
        for (int v = 0; v < NV; v++) {
            float4 t0 = __ldg(&r0[lane + 32 * v]);
            float4 t1 = __ldg(&r1[lane + 32 * v]);
            acc0[v].x += t0.x; acc0[v].y += t0.y; acc0[v].z += t0.z; acc0[v].w += t0.w;
            acc1[v].x += t1.x; acc1[v].y += t1.y; acc1[v].z += t1.z; acc1[v].w += t1.w;
        }
    }
    if (j < e) {
        const float4* r0 = (const float4*)(X + (size_t)col[j] * F);
#pragma unroll
        for (int v = 0; v < NV; v++) {
            float4 t0 = __ldg(&r0[lane + 32 * v]);
            acc0[v].x += t0.x; acc0[v].y += t0.y; acc0[v].z += t0.z; acc0[v].w += t0.w;
        }
    }
    float inv = (e > s) ? 1.0f / (float)(e - s) : 0.0f;
    float4* o = (float4*)(out + (size_t)w * F);
#pragma unroll
    for (int v = 0; v < NV; v++) {
        float4 t;
        t.x = (acc0[v].x + acc1[v].x) * inv;
        t.y = (acc0[v].y + acc1[v].y) * inv;
        t.z = (acc0[v].z + acc1[v].z) * inv;
        t.w = (acc0[v].w + acc1[v].w) * inv;
        o[lane + 32 * v] = t;
    }
}

// F = 64: one float2 per lane
__global__ __launch_bounds__(256) void agg_mean_64(const float* __restrict__ X,
                                                   const int* __restrict__ rs,
                                                   const int* __restrict__ col,
                                                   float* __restrict__ out, int ndst) {
    int w = blockIdx.x * 8 + (threadIdx.x >> 5);
    int lane = threadIdx.x & 31;
    if (w >= ndst) return;
    int s = rs[w], e = rs[w + 1];
    float2 acc0 = make_float2(0.f, 0.f), acc1 = make_float2(0.f, 0.f);
    int j = s;
    for (; j + 1 < e; j += 2) {
        float2 t0 = __ldg((const float2*)(X + (size_t)col[j] * 64) + lane);
        float2 t1 = __ldg((const float2*)(X + (size_t)col[j + 1] * 64) + lane);
        acc0.x += t0.x; acc0.y += t0.y;
        acc1.x += t1.x; acc1.y += t1.y;
    }
    if (j < e) {
        float2 t0 = __ldg((const float2*)(X + (size_t)col[j] * 64) + lane);
        acc0.x += t0.x; acc0.y += t0.y;
    }
    float inv = (e > s) ? 1.0f / (float)(e - s) : 0.0f;
    float2 t = make_float2((acc0.x + acc1.x) * inv, (acc0.y + acc1.y) * inv);
    ((float2*)(out + (size_t)w * 64))[lane] = t;
}

// ---------------- fused dual-A GEMM: C = act(A1 @ W1^T + A2 @ W2^T + b) ----------------
// W stored [N, K] row-major (as given).  N = HH = 256 fixed.  BM=BN=64, BK=16,
// 256 threads, 4x4 micro-tile per thread.
template <bool RELU>
__global__ __launch_bounds__(256) void gemm_dual_kernel(
    const float* __restrict__ A1, int K1, const float* __restrict__ W1,
    const float* __restrict__ A2, int K2, const float* __restrict__ W2,
    const float* __restrict__ bias, float* __restrict__ C, int M) {
    __shared__ __align__(16) float As[16][64];
    __shared__ __align__(16) float Ws[16][64];

    const int tid = threadIdx.x;
    const int tx = tid & 15;   // n dir
    const int ty = tid >> 4;   // m dir
    const int m0 = blockIdx.x * 64;
    const int n0 = blockIdx.y * 64;
    const int lr = tid >> 2;          // load row 0..63
    const int lk = (tid & 3) * 4;     // load k offset 0,4,8,12

    float4 acc[4];
#pragma unroll
    for (int i = 0; i < 4; i++) acc[i] = make_float4(0.f, 0.f, 0.f, 0.f);

#pragma unroll 1
    for (int pass = 0; pass < 2; pass++) {
        const float* A = pass ? A2 : A1;
        const float* W = pass ? W2 : W1;
        const int K = pass ? K2 : K1;
#pragma unroll 1
        for (int k0 = 0; k0 < K; k0 += 16) {
            float4 a4 = make_float4(0.f, 0.f, 0.f, 0.f);
            if (m0 + lr < M)
                a4 = *(const float4*)(A + (size_t)(m0 + lr) * K + k0 + lk);
            float4 w4 = *(const float4*)(W + (size_t)(n0 + lr) * K + k0 + lk);
            __syncthreads();
            As[lk + 0][lr] = a4.x; As[lk + 1][lr] = a4.y;
            As[lk + 2][lr] = a4.z; As[lk + 3][lr] = a4.w;
            Ws[lk + 0][lr] = w4.x; Ws[lk + 1][lr] = w4.y;
            Ws[lk + 2][lr] = w4.z; Ws[lk + 3][lr] = w4.w;
            __syncthreads();
#pragma unroll
            for (int k = 0; k < 16; k++) {
                float4 a = *(const float4*)&As[k][ty * 4];
                float4 b = *(const float4*)&Ws[k][tx * 4];
                acc[0].x += a.x * b.x; acc[0].y += a.x * b.y; acc[0].z += a.x * b.z; acc[0].w += a.x * b.w;
                acc[1].x += a.y * b.x; acc[1].y += a.y * b.y; acc[1].z += a.y * b.z; acc[1].w += a.y * b.w;
                acc[2].x += a.z * b.x; acc[2].y += a.z * b.y; acc[2].z += a.z * b.z; acc[2].w += a.z * b.w;
                acc[3].x += a.w * b.x; acc[3].y += a.w * b.y; acc[3].z += a.w * b.z; acc[3].w += a.w * b.w;
            }
        }
    }

    float4 bv = *(const float4*)(bias + n0 + tx * 4);
#pragma unroll
    for (int i = 0; i < 4; i++) {
        int m = m0 + ty * 4 + i;
        if (m < M) {
            float4 v = acc[i];
            v.x += bv.x; v.y += bv.y; v.z += bv.z; v.w += bv.w;
            if (RELU) {
                v.x = fmaxf(v.x, 0.f); v.y = fmaxf(v.y, 0.f);
                v.z = fmaxf(v.z, 0.f); v.w = fmaxf(v.w, 0.f);
            }
            *(float4*)(C + (size_t)m * HH + n0 + tx * 4) = v;
        }
    }
}

// ---------------- host ----------------
extern "C" void kernel_launch(void* const* d_in, const int* in_sizes, int n_in,
                              void* d_out, int out_size) {
    const float* x_user = (const float*)d_in[0];
    const float* x_item = (const float*)d_in[1];
    const int* ui_src = (const int*)d_in[2];
    const int* ui_dst = (const int*)d_in[3];
    const int* iu_src = (const int*)d_in[4];
    const int* iu_dst = (const int*)d_in[5];
    const float* W1l_ui = (const float*)d_in[6];
    const float* b1_ui  = (const float*)d_in[7];
    const float* W1r_ui = (const float*)d_in[8];
    const float* W1l_iu = (const float*)d_in[9];
    const float* b1_iu  = (const float*)d_in[10];
    const float* W1r_iu = (const float*)d_in[11];
    const float* W2l_ui = (const float*)d_in[12];
    const float* b2_ui  = (const float*)d_in[13];
    const float* W2r_ui = (const float*)d_in[14];
    const float* W2l_iu = (const float*)d_in[15];
    const float* b2_iu  = (const float*)d_in[16];
    const float* W2r_iu = (const float*)d_in[17];

    int *cnt_item, *cnt_user, *cur_item, *cur_user, *rs_item, *rs_user, *col_ui, *col_iu;
    float *agg_item, *agg_user, *h_item, *h_user, *aggH_item, *aggH_user;
    cudaGetSymbolAddress((void**)&cnt_item, g_cnt_item);
    cudaGetSymbolAddress((void**)&cnt_user, g_cnt_user);
    cudaGetSymbolAddress((void**)&cur_item, g_cur_item);
    cudaGetSymbolAddress((void**)&cur_user, g_cur_user);
    cudaGetSymbolAddress((void**)&rs_item, g_rs_item);
    cudaGetSymbolAddress((void**)&rs_user, g_rs_user);
    cudaGetSymbolAddress((void**)&col_ui, g_col_ui);
    cudaGetSymbolAddress((void**)&col_iu, g_col_iu);
    cudaGetSymbolAddress((void**)&agg_item, g_agg_item);
    cudaGetSymbolAddress((void**)&agg_user, g_agg_user);
    cudaGetSymbolAddress((void**)&h_item, g_h_item);
    cudaGetSymbolAddress((void**)&h_user, g_h_user);
    cudaGetSymbolAddress((void**)&aggH_item, g_aggH_item);
    cudaGetSymbolAddress((void**)&aggH_user, g_aggH_user);

    cudaMemsetAsync(cnt_item, 0, N_ITEMC * sizeof(int), 0);
    cudaMemsetAsync(cnt_user, 0, N_USERC * sizeof(int), 0);
    cudaMemsetAsync(cur_item, 0, N_ITEMC * sizeof(int), 0);
    cudaMemsetAsync(cur_user, 0, N_USERC * sizeof(int), 0);

    // CSR build (reused by both layers)
    count_kernel<<<(NE + 255) / 256, 256>>>(ui_dst, iu_dst);
    scan_kernel<<<2, 1024>>>();
    fill_kernel<<<(NE + 255) / 256, 256>>>(ui_src, ui_dst, iu_src, iu_dst);

    // layer 1 aggregation (original feature dims)
    agg_mean_v4<1><<<(N_ITEMC + 7) / 8, 256>>>(x_user, rs_item, col_ui, agg_item, N_ITEMC);
    agg_mean_64<<<(N_USERC + 7) / 8, 256>>>(x_item, rs_user, col_iu, agg_user, N_USERC);

    // layer 1 fused GEMM + bias + relu
    gemm_dual_kernel<true><<<dim3((N_ITEMC + 63) / 64, 4), 256>>>(
        agg_item, DU, W1l_ui, x_item, DI, W1r_ui, b1_ui, h_item, N_ITEMC);
    gemm_dual_kernel<true><<<dim3((N_USERC + 63) / 64, 4), 256>>>(
        agg_user, DI, W1l_iu, x_user, DU, W1r_iu, b1_iu, h_user, N_USERC);

    // layer 2 aggregation (H = 256)
    agg_mean_v4<2><<<(N_ITEMC + 7) / 8, 256>>>(h_user, rs_item, col_ui, aggH_item, N_ITEMC);
    agg_mean_v4<2><<<(N_USERC + 7) / 8, 256>>>(h_item, rs_user, col_iu, aggH_user, N_USERC);

    // layer 2 fused GEMM + bias (output order: out_user then out_item)
    float* out_user = (float*)d_out;
    float* out_item = out_user + (size_t)N_USERC * HH;
    gemm_dual_kernel<false><<<dim3((N_ITEMC + 63) / 64, 4), 256>>>(
        aggH_item, HH, W2l_ui, h_item, HH, W2r_ui, b2_ui, out_item, N_ITEMC);
    gemm_dual_kernel<false><<<dim3((N_USERC + 63) / 64, 4), 256>>>(
        aggH_user, HH, W2l_iu, h_user, HH, W2r_iu, b2_iu, out_user, N_USERC);
}

// round 3
// speedup vs baseline: 1.0006x; 1.0006x over previous
#include <cuda_runtime.h>

#define N_USERC 100000
#define N_ITEMC 50000
#define NE      1600000
#define DU      128
#define DI      64
#define HH      256

// ---------------- device scratch (no runtime allocation allowed) ----------------
__device__ int g_cnt_item[N_ITEMC];
__device__ int g_cnt_user[N_USERC];
__device__ int g_cur_item[N_ITEMC];
__device__ int g_cur_user[N_USERC];
__device__ int g_rs_item[N_ITEMC + 1];
__device__ int g_rs_user[N_USERC + 1];
__device__ int g_col_ui[NE];   // per item-dst: list of user srcs
__device__ int g_col_iu[NE];   // per user-dst: list of item srcs

__device__ float g_agg_item[(size_t)N_ITEMC * DU];   // mean of x_user per item
__device__ float g_agg_user[(size_t)N_USERC * DI];   // mean of x_item per user
__device__ float g_h_item[(size_t)N_ITEMC * HH];
__device__ float g_h_user[(size_t)N_USERC * HH];
__device__ float g_aggH_item[(size_t)N_ITEMC * HH];  // mean of h_user per item
__device__ float g_aggH_user[(size_t)N_USERC * HH];  // mean of h_item per user

// ---------------- CSR build ----------------
__global__ void count_kernel(const int* __restrict__ ui_dst, const int* __restrict__ iu_dst) {
    int i = blockIdx.x * blockDim.x + threadIdx.x;
    if (i < NE) {
        atomicAdd(&g_cnt_item[ui_dst[i]], 1);
        atomicAdd(&g_cnt_user[iu_dst[i]], 1);
    }
}

// Exclusive scan over degree arrays; block 0 -> items, block 1 -> users.
__global__ void scan_kernel() {
    const int* cnt = (blockIdx.x == 0) ? g_cnt_item : g_cnt_user;
    int*       rs  = (blockIdx.x == 0) ? g_rs_item  : g_rs_user;
    const int  n   = (blockIdx.x == 0) ? N_ITEMC    : N_USERC;

    __shared__ int sm[1024];
    __shared__ int running;
    if (threadIdx.x == 0) running = 0;
    __syncthreads();

    for (int base = 0; base < n; base += 1024) {
        int i = base + threadIdx.x;
        int v = (i < n) ? cnt[i] : 0;
        sm[threadIdx.x] = v;
        __syncthreads();
        // Hillis–Steele inclusive scan
        for (int off = 1; off < 1024; off <<= 1) {
            int t = (threadIdx.x >= (unsigned)off) ? sm[threadIdx.x - off] : 0;
            __syncthreads();
            sm[threadIdx.x] += t;
            __syncthreads();
        }
        if (i < n) rs[i] = running + sm[threadIdx.x] - v;   // exclusive
        int tot = sm[1023];
        __syncthreads();
        if (threadIdx.x == 0) running += tot;
        __syncthreads();
    }
    if (threadIdx.x == 0) rs[n] = running;
}

__global__ void fill_kernel(const int* __restrict__ ui_src, const int* __restrict__ ui_dst,
                            const int* __restrict__ iu_src, const int* __restrict__ iu_dst) {
    int i = blockIdx.x * blockDim.x + threadIdx.x;
    if (i >= NE) return;
    {
        int d = ui_dst[i];
        int p = atomicAdd(&g_cur_item[d], 1);
        g_col_ui[g_rs_item[d] + p] = ui_src[i];
    }
    {
        int d = iu_dst[i];
        int p = atomicAdd(&g_cur_user[d], 1);
        g_col_iu[g_rs_user[d] + p] = iu_src[i];
    }
}

// ---------------- gather-based segment mean ----------------
// One warp per destination row; F = NV*128 floats per row, float4 per lane per NV.
template <int NV>
__global__ __launch_bounds__(256) void agg_mean_v4(const float* __restrict__ X,
                                                   const int* __restrict__ rs,
                                                   const int* __restrict__ col,
                                                   float* __restrict__ out, int ndst) {
    int w = blockIdx.x * 8 + (threadIdx.x >> 5);
    int lane = threadIdx.x & 31;
    if (w >= ndst) return;
    int s = rs[w], e = rs[w + 1];
    constexpr int F = NV * 128;

    float4 acc0[NV], acc1[NV];
#pragma unroll
    for (int v = 0; v < NV; v++) {
        acc0[v] = make_float4(0.f, 0.f, 0.f, 0.f);
        acc1[v] = make_float4(0.f, 0.f, 0.f, 0.f);
    }
    int j = s;
    for (; j + 1 < e; j += 2) {
        const float4* r0 = (const float4*)(X + (size_t)col[j] * F);
        const float4* r1 = (const float4*)(X + (size_t)col[j + 1] * F);
#pragma unroll
        for (int v = 0; v < NV; v++) {
            float4 t0 = __ldg(&r0[lane + 32 * v]);
            float4 t1 = __ldg(&r1[lane + 32 * v]);
            acc0[v].x += t0.x; acc0[v].y += t0.y; acc0[v].z += t0.z; acc0[v].w += t0.w;
            acc1[v].x += t1.x; acc1[v].y += t1.y; acc1[v].z += t1.z; acc1[v].w += t1.w;
        }
    }
    if (j < e) {
        const float4* r0 = (const float4*)(X + (size_t)col[j] * F);
#pragma unroll
        for (int v = 0; v < NV; v++) {
            float4 t0 = __ldg(&r0[lane + 32 * v]);
            acc0[v].x += t0.x; acc0[v].y += t0.y; acc0[v].z += t0.z; acc0[v].w += t0.w;
        }
    }
    float inv = (e > s) ? 1.0f / (float)(e - s) : 0.0f;
    float4* o = (float4*)(out + (size_t)w * F);
#pragma unroll
    for (int v = 0; v < NV; v++) {
        float4 t;
        t.x = (acc0[v].x + acc1[v].x) * inv;
        t.y = (acc0[v].y + acc1[v].y) * inv;
        t.z = (acc0[v].z + acc1[v].z) * inv;
        t.w = (acc0[v].w + acc1[v].w) * inv;
        o[lane + 32 * v] = t;
    }
}

// F = 64: one float2 per lane
__global__ __launch_bounds__(256) void agg_mean_64(const float* __restrict__ X,
                                                   const int* __restrict__ rs,
                                                   const int* __restrict__ col,
                                                   float* __restrict__ out, int ndst) {
    int w = blockIdx.x * 8 + (threadIdx.x >> 5);
    int lane = threadIdx.x & 31;
    if (w >= ndst) return;
    int s = rs[w], e = rs[w + 1];
    float2 acc0 = make_float2(0.f, 0.f), acc1 = make_float2(0.f, 0.f);
    int j = s;
    for (; j + 1 < e; j += 2) {
        float2 t0 = __ldg((const float2*)(X + (size_t)col[j] * 64) + lane);
        float2 t1 = __ldg((const float2*)(X + (size_t)col[j + 1] * 64) + lane);
        acc0.x += t0.x; acc0.y += t0.y;
        acc1.x += t1.x; acc1.y += t1.y;
    }
    if (j < e) {
        float2 t0 = __ldg((const float2*)(X + (size_t)col[j] * 64) + lane);
        acc0.x += t0.x; acc0.y += t0.y;
    }
    float inv = (e > s) ? 1.0f / (float)(e - s) : 0.0f;
    float2 t = make_float2((acc0.x + acc1.x) * inv, (acc0.y + acc1.y) * inv);
    ((float2*)(out + (size_t)w * 64))[lane] = t;
}

// ---------------- fused dual-A GEMM: C = act(A1 @ W1^T + A2 @ W2^T + b) ----------------
// W stored [N, K] row-major (as given).  N = HH = 256 fixed.  BM=BN=64, BK=16,
// 256 threads, 4x4 micro-tile per thread.
template <bool RELU>
__global__ __launch_bounds__(256) void gemm_dual_kernel(
    const float* __restrict__ A1, int K1, const float* __restrict__ W1,
    const float* __restrict__ A2, int K2, const float* __restrict__ W2,
    const float* __restrict__ bias, float* __restrict__ C, int M) {
    __shared__ __align__(16) float As[16][64];
    __shared__ __align__(16) float Ws[16][64];

    const int tid = threadIdx.x;
    const int tx = tid & 15;   // n dir
    const int ty = tid >> 4;   // m dir
    const int m0 = blockIdx.x * 64;
    const int n0 = blockIdx.y * 64;
    const int lr = tid >> 2;          // load row 0..63
    const int lk = (tid & 3) * 4;     // load k offset 0,4,8,12

    float4 acc[4];
#pragma unroll
    for (int i = 0; i < 4; i++) acc[i] = make_float4(0.f, 0.f, 0.f, 0.f);

#pragma unroll 1
    for (int pass = 0; pass < 2; pass++) {
        const float* A = pass ? A2 : A1;
        const float* W = pass ? W2 : W1;
        const int K = pass ? K2 : K1;
#pragma unroll 1
        for (int k0 = 0; k0 < K; k0 += 16) {
            float4 a4 = make_float4(0.f, 0.f, 0.f, 0.f);
            if (m0 + lr < M)
                a4 = *(const float4*)(A + (size_t)(m0 + lr) * K + k0 + lk);
            float4 w4 = *(const float4*)(W + (size_t)(n0 + lr) * K + k0 + lk);
            __syncthreads();
            As[lk + 0][lr] = a4.x; As[lk + 1][lr] = a4.y;
            As[lk + 2][lr] = a4.z; As[lk + 3][lr] = a4.w;
            Ws[lk + 0][lr] = w4.x; Ws[lk + 1][lr] = w4.y;
            Ws[lk + 2][lr] = w4.z; Ws[lk + 3][lr] = w4.w;
            __syncthreads();
#pragma unroll
            for (int k = 0; k < 16; k++) {
                float4 a = *(const float4*)&As[k][ty * 4];
                float4 b = *(const float4*)&Ws[k][tx * 4];
                acc[0].x += a.x * b.x; acc[0].y += a.x * b.y; acc[0].z += a.x * b.z; acc[0].w += a.x * b.w;
                acc[1].x += a.y * b.x; acc[1].y += a.y * b.y; acc[1].z += a.y * b.z; acc[1].w += a.y * b.w;
                acc[2].x += a.z * b.x; acc[2].y += a.z * b.y; acc[2].z += a.z * b.z; acc[2].w += a.z * b.w;
                acc[3].x += a.w * b.x; acc[3].y += a.w * b.y; acc[3].z += a.w * b.z; acc[3].w += a.w * b.w;
            }
        }
    }

    float4 bv = *(const float4*)(bias + n0 + tx * 4);
#pragma unroll
    for (int i = 0; i < 4; i++) {
        int m = m0 + ty * 4 + i;
        if (m < M) {
            float4 v = acc[i];
            v.x += bv.x; v.y += bv.y; v.z += bv.z; v.w += bv.w;
            if (RELU) {
                v.x = fmaxf(v.x, 0.f); v.y = fmaxf(v.y, 0.f);
                v.z = fmaxf(v.z, 0.f); v.w = fmaxf(v.w, 0.f);
            }
            *(float4*)(C + (size_t)m * HH + n0 + tx * 4) = v;
        }
    }
}

// ---------------- host ----------------
extern "C" void kernel_launch(void* const* d_in, const int* in_sizes, int n_in,
                              void* d_out, int out_size) {
    const float* x_user = (const float*)d_in[0];
    const float* x_item = (const float*)d_in[1];
    const int* ui_src = (const int*)d_in[2];
    const int* ui_dst = (const int*)d_in[3];
    const int* iu_src = (const int*)d_in[4];
    const int* iu_dst = (const int*)d_in[5];
    const float* W1l_ui = (const float*)d_in[6];
    const float* b1_ui  = (const float*)d_in[7];
    const float* W1r_ui = (const float*)d_in[8];
    const float* W1l_iu = (const float*)d_in[9];
    const float* b1_iu  = (const float*)d_in[10];
    const float* W1r_iu = (const float*)d_in[11];
    const float* W2l_ui = (const float*)d_in[12];
    const float* b2_ui  = (const float*)d_in[13];
    const float* W2r_ui = (const float*)d_in[14];
    const float* W2l_iu = (const float*)d_in[15];
    const float* b2_iu  = (const float*)d_in[16];
    const float* W2r_iu = (const float*)d_in[17];

    int *cnt_item, *cnt_user, *cur_item, *cur_user, *rs_item, *rs_user, *col_ui, *col_iu;
    float *agg_item, *agg_user, *h_item, *h_user, *aggH_item, *aggH_user;
    cudaGetSymbolAddress((void**)&cnt_item, g_cnt_item);
    cudaGetSymbolAddress((void**)&cnt_user, g_cnt_user);
    cudaGetSymbolAddress((void**)&cur_item, g_cur_item);
    cudaGetSymbolAddress((void**)&cur_user, g_cur_user);
    cudaGetSymbolAddress((void**)&rs_item, g_rs_item);
    cudaGetSymbolAddress((void**)&rs_user, g_rs_user);
    cudaGetSymbolAddress((void**)&col_ui, g_col_ui);
    cudaGetSymbolAddress((void**)&col_iu, g_col_iu);
    cudaGetSymbolAddress((void**)&agg_item, g_agg_item);
    cudaGetSymbolAddress((void**)&agg_user, g_agg_user);
    cudaGetSymbolAddress((void**)&h_item, g_h_item);
    cudaGetSymbolAddress((void**)&h_user, g_h_user);
    cudaGetSymbolAddress((void**)&aggH_item, g_aggH_item);
    cudaGetSymbolAddress((void**)&aggH_user, g_aggH_user);

    cudaMemsetAsync(cnt_item, 0, N_ITEMC * sizeof(int), 0);
    cudaMemsetAsync(cnt_user, 0, N_USERC * sizeof(int), 0);
    cudaMemsetAsync(cur_item, 0, N_ITEMC * sizeof(int), 0);
    cudaMemsetAsync(cur_user, 0, N_USERC * sizeof(int), 0);

    // CSR build (reused by both layers)
    count_kernel<<<(NE + 255) / 256, 256>>>(ui_dst, iu_dst);
    scan_kernel<<<2, 1024>>>();
    fill_kernel<<<(NE + 255) / 256, 256>>>(ui_src, ui_dst, iu_src, iu_dst);

    // layer 1 aggregation (original feature dims)
    agg_mean_v4<1><<<(N_ITEMC + 7) / 8, 256>>>(x_user, rs_item, col_ui, agg_item, N_ITEMC);
    agg_mean_64<<<(N_USERC + 7) / 8, 256>>>(x_item, rs_user, col_iu, agg_user, N_USERC);

    // layer 1 fused GEMM + bias + relu
    gemm_dual_kernel<true><<<dim3((N_ITEMC + 63) / 64, 4), 256>>>(
        agg_item, DU, W1l_ui, x_item, DI, W1r_ui, b1_ui, h_item, N_ITEMC);
    gemm_dual_kernel<true><<<dim3((N_USERC + 63) / 64, 4), 256>>>(
        agg_user, DI, W1l_iu, x_user, DU, W1r_iu, b1_iu, h_user, N_USERC);

    // layer 2 aggregation (H = 256)
    agg_mean_v4<2><<<(N_ITEMC + 7) / 8, 256>>>(h_user, rs_item, col_ui, aggH_item, N_ITEMC);
    agg_mean_v4<2><<<(N_USERC + 7) / 8, 256>>>(h_item, rs_user, col_iu, aggH_user, N_USERC);

    // layer 2 fused GEMM + bias (output order: out_user then out_item)
    float* out_user = (float*)d_out;
    float* out_item = out_user + (size_t)N_USERC * HH;
    gemm_dual_kernel<false><<<dim3((N_ITEMC + 63) / 64, 4), 256>>>(
        aggH_item, HH, W2l_ui, h_item, HH, W2r_ui, b2_ui, out_item, N_ITEMC);
    gemm_dual_kernel<false><<<dim3((N_USERC + 63) / 64, 4), 256>>>(
        aggH_user, HH, W2l_iu, h_user, HH, W2r_iu, b2_iu, out_user, N_USERC);
}

// round 5
// speedup vs baseline: 1.7634x; 1.7623x over previous
#include <cuda_runtime.h>
#include <cstdint>

#define N_USERC 100000
#define N_ITEMC 50000
#define NE      1600000
#define DU      128
#define DI      64
#define HH      256

// ---------------- device scratch (no runtime allocation allowed) ----------------
__device__ int g_cnt_item[N_ITEMC];
__device__ int g_cnt_user[N_USERC];
__device__ int g_cur_item[N_ITEMC];
__device__ int g_cur_user[N_USERC];
__device__ int g_rs_item[N_ITEMC + 1];
__device__ int g_rs_user[N_USERC + 1];
__device__ int g_col_ui[NE];
__device__ int g_col_iu[NE];

__device__ float g_agg_item[(size_t)N_ITEMC * DU];
__device__ float g_agg_user[(size_t)N_USERC * DI];
__device__ float g_h_item[(size_t)N_ITEMC * HH];
__device__ float g_h_user[(size_t)N_USERC * HH];
__device__ float g_aggH_item[(size_t)N_ITEMC * HH];
__device__ float g_aggH_user[(size_t)N_USERC * HH];

// ---------------- CSR build ----------------
__global__ void count_kernel(const int* __restrict__ ui_dst, const int* __restrict__ iu_dst) {
    int i = blockIdx.x * blockDim.x + threadIdx.x;
    if (i < NE) {
        atomicAdd(&g_cnt_item[ui_dst[i]], 1);
        atomicAdd(&g_cnt_user[iu_dst[i]], 1);
    }
}

__global__ void scan_kernel() {
    const int* cnt = (blockIdx.x == 0) ? g_cnt_item : g_cnt_user;
    int*       rs  = (blockIdx.x == 0) ? g_rs_item  : g_rs_user;
    const int  n   = (blockIdx.x == 0) ? N_ITEMC    : N_USERC;

    __shared__ int sm[1024];
    __shared__ int running;
    if (threadIdx.x == 0) running = 0;
    __syncthreads();

    for (int base = 0; base < n; base += 1024) {
        int i = base + threadIdx.x;
        int v = (i < n) ? cnt[i] : 0;
        sm[threadIdx.x] = v;
        __syncthreads();
        for (int off = 1; off < 1024; off <<= 1) {
            int t = (threadIdx.x >= (unsigned)off) ? sm[threadIdx.x - off] : 0;
            __syncthreads();
            sm[threadIdx.x] += t;
            __syncthreads();
        }
        if (i < n) rs[i] = running + sm[threadIdx.x] - v;
        int tot = sm[1023];
        __syncthreads();
        if (threadIdx.x == 0) running += tot;
        __syncthreads();
    }
    if (threadIdx.x == 0) rs[n] = running;
}

__global__ void fill_kernel(const int* __restrict__ ui_src, const int* __restrict__ ui_dst,
                            const int* __restrict__ iu_src, const int* __restrict__ iu_dst) {
    int i = blockIdx.x * blockDim.x + threadIdx.x;
    if (i >= NE) return;
    {
        int d = ui_dst[i];
        int p = atomicAdd(&g_cur_item[d], 1);
        g_col_ui[g_rs_item[d] + p] = ui_src[i];
    }
    {
        int d = iu_dst[i];
        int p = atomicAdd(&g_cur_user[d], 1);
        g_col_iu[g_rs_user[d] + p] = iu_src[i];
    }
}

// ---------------- gather-based segment mean ----------------
template <int NV>
__global__ __launch_bounds__(256) void agg_mean_v4(const float* __restrict__ X,
                                                   const int* __restrict__ rs,
                                                   const int* __restrict__ col,
                                                   float* __restrict__ out, int ndst) {
    int w = blockIdx.x * 8 + (threadIdx.x >> 5);
    int lane = threadIdx.x & 31;
    if (w >= ndst) return;
    int s = rs[w], e = rs[w + 1];
    constexpr int F = NV * 128;

    float4 acc0[NV], acc1[NV];
#pragma unroll
    for (int v = 0; v < NV; v++) {
        acc0[v] = make_float4(0.f, 0.f, 0.f, 0.f);
        acc1[v] = make_float4(0.f, 0.f, 0.f, 0.f);
    }
    int j = s;
    for (; j + 1 < e; j += 2) {
        const float4* r0 = (const float4*)(X + (size_t)col[j] * F);
        const float4* r1 = (const float4*)(X + (size_t)col[j + 1] * F);
#pragma unroll
        for (int v = 0; v < NV; v++) {
            float4 t0 = __ldg(&r0[lane + 32 * v]);
            float4 t1 = __ldg(&r1[lane + 32 * v]);
            acc0[v].x += t0.x; acc0[v].y += t0.y; acc0[v].z += t0.z; acc0[v].w += t0.w;
            acc1[v].x += t1.x; acc1[v].y += t1.y; acc1[v].z += t1.z; acc1[v].w += t1.w;
        }
    }
    if (j < e) {
        const float4* r0 = (const float4*)(X + (size_t)col[j] * F);
#pragma unroll
        for (int v = 0; v < NV; v++) {
            float4 t0 = __ldg(&r0[lane + 32 * v]);
            acc0[v].x += t0.x; acc0[v].y += t0.y; acc0[v].z += t0.z; acc0[v].w += t0.w;
        }
    }
    float inv = (e > s) ? 1.0f / (float)(e - s) : 0.0f;
    float4* o = (float4*)(out + (size_t)w * F);
#pragma unroll
    for (int v = 0; v < NV; v++) {
        float4 t;
        t.x = (acc0[v].x + acc1[v].x) * inv;
        t.y = (acc0[v].y + acc1[v].y) * inv;
        t.z = (acc0[v].z + acc1[v].z) * inv;
        t.w = (acc0[v].w + acc1[v].w) * inv;
        o[lane + 32 * v] = t;
    }
}

__global__ __launch_bounds__(256) void agg_mean_64(const float* __restrict__ X,
                                                   const int* __restrict__ rs,
                                                   const int* __restrict__ col,
                                                   float* __restrict__ out, int ndst) {
    int w = blockIdx.x * 8 + (threadIdx.x >> 5);
    int lane = threadIdx.x & 31;
    if (w >= ndst) return;
    int s = rs[w], e = rs[w + 1];
    float2 acc0 = make_float2(0.f, 0.f), acc1 = make_float2(0.f, 0.f);
    int j = s;
    for (; j + 1 < e; j += 2) {
        float2 t0 = __ldg((const float2*)(X + (size_t)col[j] * 64) + lane);
        float2 t1 = __ldg((const float2*)(X + (size_t)col[j + 1] * 64) + lane);
        acc0.x += t0.x; acc0.y += t0.y;
        acc1.x += t1.x; acc1.y += t1.y;
    }
    if (j < e) {
        float2 t0 = __ldg((const float2*)(X + (size_t)col[j] * 64) + lane);
        acc0.x += t0.x; acc0.y += t0.y;
    }
    float inv = (e > s) ? 1.0f / (float)(e - s) : 0.0f;
    float2 t = make_float2((acc0.x + acc1.x) * inv, (acc0.y + acc1.y) * inv);
    ((float2*)(out + (size_t)w * 64))[lane] = t;
}

// ================= tf32 mma.sync dual-A GEMM =================
// C[M,256] = act(A1[M,K1] @ W1[256,K1]^T + A2[M,K2] @ W2[256,K2]^T + bias)
// CTA tile: 128x128 (grid.y = 2 covers N=256). BK=32, 2-stage SMEM ping-pong.
// 8 warps, 2x4 grid, warp tile 64x32, mma.m16n8k8.tf32.
//
// SMEM is stored PERMUTED into fragment order:
//  A: per (m-tile mt 0..7, k-step ks 0..3): 32 lanes x 4 f32 (a0..a3) contiguous
//     -> fragment load = one LDS.128 at lane*16.
//  B: per (n-tile nt 0..15, ks 0..3): 32 lanes x 2 f32 (b0,b1)
//     -> fragment load = one LDS.64 at lane*8.

#define GEMM_BK     32
#define A_STAGE_B   16384                  // 128 x 32 f32
#define B_STAGE_B   16384                  // 128 x 32 f32
#define STAGE_B     (A_STAGE_B + B_STAGE_B)
#define GEMM_SMEM   (2 * STAGE_B)          // 64 KB dynamic

__device__ __forceinline__ uint32_t f2tf32(float x) {
    uint32_t r;
    asm("cvt.rna.tf32.f32 %0, %1;" : "=r"(r) : "f"(x));
    return r;
}

__device__ __forceinline__ uint32_t smem_u32(const void* p) {
    uint32_t a;
    asm("{ .reg .u64 t; cvta.to.shared.u64 t, %1; cvt.u32.u64 %0, t; }" : "=r"(a) : "l"(p));
    return a;
}

__device__ __forceinline__ void mma_tf32(float* d, const uint32_t* a, const uint32_t* b) {
    asm volatile(
        "mma.sync.aligned.m16n8k8.row.col.f32.tf32.tf32.f32 "
        "{%0,%1,%2,%3}, {%4,%5,%6,%7}, {%8,%9}, {%0,%1,%2,%3};"
        : "+f"(d[0]), "+f"(d[1]), "+f"(d[2]), "+f"(d[3])
        : "r"(a[0]), "r"(a[1]), "r"(a[2]), "r"(a[3]), "r"(b[0]), "r"(b[1]));
}

__device__ __forceinline__ void sts32(uint32_t addr, uint32_t v) {
    asm volatile("st.shared.b32 [%0], %1;" :: "r"(addr), "r"(v) : "memory");
}
__device__ __forceinline__ void lds128(uint32_t* r, uint32_t addr) {
    asm volatile("ld.shared.v4.b32 {%0,%1,%2,%3}, [%4];"
                 : "=r"(r[0]), "=r"(r[1]), "=r"(r[2]), "=r"(r[3]) : "r"(addr) : "memory");
}
__device__ __forceinline__ void lds64(uint32_t* r, uint32_t addr) {
    asm volatile("ld.shared.v2.b32 {%0,%1}, [%2];"
                 : "=r"(r[0]), "=r"(r[1]) : "r"(addr) : "memory");
}

template <bool RELU>
__global__ __launch_bounds__(256, 1) void gemm_mma_kernel(
    const float* __restrict__ A1, int K1, const float* __restrict__ W1,
    const float* __restrict__ A2, int K2, const float* __restrict__ W2,
    const float* __restrict__ bias, float* __restrict__ C, int M) {
    extern __shared__ __align__(16) char dsmem[];
    const uint32_t smem = smem_u32(dsmem);

    const int tid = threadIdx.x;
    const int wid = tid >> 5;
    const int lane = tid & 31;
    const int warp_m = wid >> 2;   // 0..1 (64 rows each)
    const int warp_n = wid & 3;    // 0..3 (32 cols each)
    const int m0 = blockIdx.x * 128;
    const int n0 = blockIdx.y * 128;

    // ---- writer-side precomputed offsets ----
    const int r0 = tid >> 3;       // base row 0..31 (row_q = r0 + 32q)
    const int c4 = tid & 7;        // float4 column within BK (fixed across q)
    const int wks = c4 >> 1;
    const int wkh = c4 & 1;
    // A store: block (mt*4+ks), lane (g8*4+j), reg ri = wkh*2 + rhalf
    const uint32_t aoff0 = (uint32_t)(((((r0 >> 4) * 4 + wks) * 32) + (r0 & 7) * 4) * 16
                                      + (wkh * 2 + ((r0 >> 3) & 1)) * 4);
    // B store: block (nt*4+ks), lane (g*4+j), reg ri = wkh
    const uint32_t boff0 = (uint32_t)(((((r0 >> 3) * 4 + wks) * 32) + (r0 & 7) * 4) * 8
                                      + wkh * 4);

    float acc[4][4][4];
#pragma unroll
    for (int i = 0; i < 4; i++)
#pragma unroll
        for (int j = 0; j < 4; j++)
#pragma unroll
            for (int k = 0; k < 4; k++) acc[i][j][k] = 0.f;

    const int n1 = K1 / GEMM_BK;
    const int n2 = K2 / GEMM_BK;
    const int T = n1 + n2;

    float4 aR[4], bR[4];

    // ---- global load of iteration `it` into registers ----
    auto load_g = [&](int it) {
        const float* A; const float* W; int K, k0;
        if (it < n1) { A = A1; W = W1; K = K1; k0 = it * GEMM_BK; }
        else         { A = A2; W = W2; K = K2; k0 = (it - n1) * GEMM_BK; }
        const int cc = k0 + c4 * 4;
#pragma unroll
        for (int q = 0; q < 4; q++) {
            const int row = r0 + 32 * q;
            aR[q] = (m0 + row < M)
                  ? *(const float4*)(A + (size_t)(m0 + row) * K + cc)
                  : make_float4(0.f, 0.f, 0.f, 0.f);
            bR[q] = *(const float4*)(W + (size_t)(n0 + row) * K + cc);
        }
    };

    // ---- store staged registers to SMEM stage s (tf32-rounded, permuted) ----
    auto store_s = [&](int s) {
        const uint32_t sA = smem + s * STAGE_B;
        const uint32_t sB = sA + A_STAGE_B;
#pragma unroll
        for (int q = 0; q < 4; q++) {
            const uint32_t a0 = sA + aoff0 + 4096u * q;
            sts32(a0 +  0, f2tf32(aR[q].x));
            sts32(a0 + 16, f2tf32(aR[q].y));
            sts32(a0 + 32, f2tf32(aR[q].z));
            sts32(a0 + 48, f2tf32(aR[q].w));
            const uint32_t b0 = sB + boff0 + 4096u * q;
            sts32(b0 +  0, f2tf32(bR[q].x));
            sts32(b0 +  8, f2tf32(bR[q].y));
            sts32(b0 + 16, f2tf32(bR[q].z));
            sts32(b0 + 24, f2tf32(bR[q].w));
        }
    };

    // ---- compute one BK stage from SMEM ----
    auto compute_s = [&](int s) {
        const uint32_t sA = smem + s * STAGE_B;
        const uint32_t sB = sA + A_STAGE_B;
#pragma unroll
        for (int ks = 0; ks < 4; ks++) {
            uint32_t af[4][4], bf[4][2];
#pragma unroll
            for (int i = 0; i < 4; i++)
                lds128(af[i], sA + (uint32_t)((((warp_m * 4 + i) * 4 + ks) * 32 + lane) * 16));
#pragma unroll
            for (int j = 0; j < 4; j++)
                lds64(bf[j], sB + (uint32_t)((((warp_n * 4 + j) * 4 + ks) * 32 + lane) * 8));
#pragma unroll
            for (int i = 0; i < 4; i++)
#pragma unroll
                for (int j = 0; j < 4; j++)
                    mma_tf32(acc[i][j], af[i], bf[j]);
        }
    };

    // ---- pipelined main loop ----
    load_g(0);
    store_s(0);
    __syncthreads();
    int s = 0;
#pragma unroll 1
    for (int it = 0; it < T; it++) {
        if (it + 1 < T) load_g(it + 1);
        compute_s(s);
        if (it + 1 < T) store_s(1 - s);
        __syncthreads();
        s ^= 1;
    }

    // ---- epilogue: bias (+relu), direct global store ----
    const int g = lane >> 2;
    const int t = lane & 3;
#pragma unroll
    for (int j = 0; j < 4; j++) {
        const int nb = n0 + warp_n * 32 + j * 8 + t * 2;
        const float bx = bias[nb], by = bias[nb + 1];
#pragma unroll
        for (int i = 0; i < 4; i++) {
            const int rlo = m0 + warp_m * 64 + i * 16 + g;
            if (rlo < M) {
                float2 v = make_float2(acc[i][j][0] + bx, acc[i][j][1] + by);
                if (RELU) { v.x = fmaxf(v.x, 0.f); v.y = fmaxf(v.y, 0.f); }
                *(float2*)(C + (size_t)rlo * HH + nb) = v;
            }
            const int rhi = rlo + 8;
            if (rhi < M) {
                float2 v = make_float2(acc[i][j][2] + bx, acc[i][j][3] + by);
                if (RELU) { v.x = fmaxf(v.x, 0.f); v.y = fmaxf(v.y, 0.f); }
                *(float2*)(C + (size_t)rhi * HH + nb) = v;
            }
        }
    }
}

// ---------------- host ----------------
extern "C" void kernel_launch(void* const* d_in, const int* in_sizes, int n_in,
                              void* d_out, int out_size) {
    const float* x_user = (const float*)d_in[0];
    const float* x_item = (const float*)d_in[1];
    const int* ui_src = (const int*)d_in[2];
    const int* ui_dst = (const int*)d_in[3];
    const int* iu_src = (const int*)d_in[4];
    const int* iu_dst = (const int*)d_in[5];
    const float* W1l_ui = (const float*)d_in[6];
    const float* b1_ui  = (const float*)d_in[7];
    const float* W1r_ui = (const float*)d_in[8];
    const float* W1l_iu = (const float*)d_in[9];
    const float* b1_iu  = (const float*)d_in[10];
    const float* W1r_iu = (const float*)d_in[11];
    const float* W2l_ui = (const float*)d_in[12];
    const float* b2_ui  = (const float*)d_in[13];
    const float* W2r_ui = (const float*)d_in[14];
    const float* W2l_iu = (const float*)d_in[15];
    const float* b2_iu  = (const float*)d_in[16];
    const float* W2r_iu = (const float*)d_in[17];

    int *cnt_item, *cnt_user, *cur_item, *cur_user, *rs_item, *rs_user, *col_ui, *col_iu;
    float *agg_item, *agg_user, *h_item, *h_user, *aggH_item, *aggH_user;
    cudaGetSymbolAddress((void**)&cnt_item, g_cnt_item);
    cudaGetSymbolAddress((void**)&cnt_user, g_cnt_user);
    cudaGetSymbolAddress((void**)&cur_item, g_cur_item);
    cudaGetSymbolAddress((void**)&cur_user, g_cur_user);
    cudaGetSymbolAddress((void**)&rs_item, g_rs_item);
    cudaGetSymbolAddress((void**)&rs_user, g_rs_user);
    cudaGetSymbolAddress((void**)&col_ui, g_col_ui);
    cudaGetSymbolAddress((void**)&col_iu, g_col_iu);
    cudaGetSymbolAddress((void**)&agg_item, g_agg_item);
    cudaGetSymbolAddress((void**)&agg_user, g_agg_user);
    cudaGetSymbolAddress((void**)&h_item, g_h_item);
    cudaGetSymbolAddress((void**)&h_user, g_h_user);
    cudaGetSymbolAddress((void**)&aggH_item, g_aggH_item);
    cudaGetSymbolAddress((void**)&aggH_user, g_aggH_user);

    cudaFuncSetAttribute(gemm_mma_kernel<true>,
                         cudaFuncAttributeMaxDynamicSharedMemorySize, GEMM_SMEM);
    cudaFuncSetAttribute(gemm_mma_kernel<false>,
                         cudaFuncAttributeMaxDynamicSharedMemorySize, GEMM_SMEM);

    cudaMemsetAsync(cnt_item, 0, N_ITEMC * sizeof(int), 0);
    cudaMemsetAsync(cnt_user, 0, N_USERC * sizeof(int), 0);
    cudaMemsetAsync(cur_item, 0, N_ITEMC * sizeof(int), 0);
    cudaMemsetAsync(cur_user, 0, N_USERC * sizeof(int), 0);

    // CSR build (reused by both layers)
    count_kernel<<<(NE + 255) / 256, 256>>>(ui_dst, iu_dst);
    scan_kernel<<<2, 1024>>>();
    fill_kernel<<<(NE + 255) / 256, 256>>>(ui_src, ui_dst, iu_src, iu_dst);

    // layer 1 aggregation
    agg_mean_v4<1><<<(N_ITEMC + 7) / 8, 256>>>(x_user, rs_item, col_ui, agg_item, N_ITEMC);
    agg_mean_64<<<(N_USERC + 7) / 8, 256>>>(x_item, rs_user, col_iu, agg_user, N_USERC);

    // layer 1 fused GEMM + bias + relu (tf32 tensor cores)
    gemm_mma_kernel<true><<<dim3((N_ITEMC + 127) / 128, 2), 256, GEMM_SMEM>>>(
        agg_item, DU, W1l_ui, x_item, DI, W1r_ui, b1_ui, h_item, N_ITEMC);
    gemm_mma_kernel<true><<<dim3((N_USERC + 127) / 128, 2), 256, GEMM_SMEM>>>(
        agg_user, DI, W1l_iu, x_user, DU, W1r_iu, b1_iu, h_user, N_USERC);

    // layer 2 aggregation (H = 256)
    agg_mean_v4<2><<<(N_ITEMC + 7) / 8, 256>>>(h_user, rs_item, col_ui, aggH_item, N_ITEMC);
    agg_mean_v4<2><<<(N_USERC + 7) / 8, 256>>>(h_item, rs_user, col_iu, aggH_user, N_USERC);

    // layer 2 fused GEMM + bias (output order: out_user then out_item)
    float* out_user = (float*)d_out;
    float* out_item = out_user + (size_t)N_USERC * HH;
    gemm_mma_kernel<false><<<dim3((N_ITEMC + 127) / 128, 2), 256, GEMM_SMEM>>>(
        aggH_item, HH, W2l_ui, h_item, HH, W2r_ui, b2_ui, out_item, N_ITEMC);
    gemm_mma_kernel<false><<<dim3((N_USERC + 127) / 128, 2), 256, GEMM_SMEM>>>(
        aggH_user, HH, W2l_iu, h_user, HH, W2r_iu, b2_iu, out_user, N_USERC);
}

// round 6
// speedup vs baseline: 1.8915x; 1.0726x over previous
#include <cuda_runtime.h>
#include <cstdint>

#define N_USERC 100000
#define N_ITEMC 50000
#define NE      1600000
#define DU      128
#define DI      64
#define HH      256

// ---------------- device scratch (no runtime allocation allowed) ----------------
__device__ int g_cnt_item[N_ITEMC];
__device__ int g_cnt_user[N_USERC];
__device__ int g_cur_item[N_ITEMC];
__device__ int g_cur_user[N_USERC];
__device__ int g_rs_item[N_ITEMC + 1];
__device__ int g_rs_user[N_USERC + 1];
__device__ int g_col_ui[NE];
__device__ int g_col_iu[NE];

__device__ float g_agg_item[(size_t)N_ITEMC * DU];
__device__ float g_agg_user[(size_t)N_USERC * DI];
__device__ float g_h_item[(size_t)N_ITEMC * HH];
__device__ float g_h_user[(size_t)N_USERC * HH];
__device__ float g_aggH_item[(size_t)N_ITEMC * HH];
__device__ float g_aggH_user[(size_t)N_USERC * HH];

// ---------------- CSR build ----------------
__global__ void count_kernel(const int* __restrict__ ui_dst, const int* __restrict__ iu_dst) {
    int i = blockIdx.x * blockDim.x + threadIdx.x;
    if (i < NE) {
        atomicAdd(&g_cnt_item[ui_dst[i]], 1);
        atomicAdd(&g_cnt_user[iu_dst[i]], 1);
    }
}

__global__ void scan_kernel() {
    const int* cnt = (blockIdx.x == 0) ? g_cnt_item : g_cnt_user;
    int*       rs  = (blockIdx.x == 0) ? g_rs_item  : g_rs_user;
    const int  n   = (blockIdx.x == 0) ? N_ITEMC    : N_USERC;

    __shared__ int sm[1024];
    __shared__ int running;
    if (threadIdx.x == 0) running = 0;
    __syncthreads();

    for (int base = 0; base < n; base += 1024) {
        int i = base + threadIdx.x;
        int v = (i < n) ? cnt[i] : 0;
        sm[threadIdx.x] = v;
        __syncthreads();
        for (int off = 1; off < 1024; off <<= 1) {
            int t = (threadIdx.x >= (unsigned)off) ? sm[threadIdx.x - off] : 0;
            __syncthreads();
            sm[threadIdx.x] += t;
            __syncthreads();
        }
        if (i < n) rs[i] = running + sm[threadIdx.x] - v;
        int tot = sm[1023];
        __syncthreads();
        if (threadIdx.x == 0) running += tot;
        __syncthreads();
    }
    if (threadIdx.x == 0) rs[n] = running;
}

__global__ void fill_kernel(const int* __restrict__ ui_src, const int* __restrict__ ui_dst,
                            const int* __restrict__ iu_src, const int* __restrict__ iu_dst) {
    int i = blockIdx.x * blockDim.x + threadIdx.x;
    if (i >= NE) return;
    {
        int d = ui_dst[i];
        int p = atomicAdd(&g_cur_item[d], 1);
        g_col_ui[g_rs_item[d] + p] = ui_src[i];
    }
    {
        int d = iu_dst[i];
        int p = atomicAdd(&g_cur_user[d], 1);
        g_col_iu[g_rs_user[d] + p] = iu_src[i];
    }
}

// ---------------- gather-based segment mean (4-way unrolled for MLP) ----------------
template <int NV>
__global__ __launch_bounds__(256) void agg_mean_v4(const float* __restrict__ X,
                                                   const int* __restrict__ rs,
                                                   const int* __restrict__ col,
                                                   float* __restrict__ out, int ndst) {
    int w = blockIdx.x * 8 + (threadIdx.x >> 5);
    int lane = threadIdx.x & 31;
    if (w >= ndst) return;
    int s = rs[w], e = rs[w + 1];
    constexpr int F = NV * 128;

    float4 acc[4][NV];
#pragma unroll
    for (int u = 0; u < 4; u++)
#pragma unroll
        for (int v = 0; v < NV; v++) acc[u][v] = make_float4(0.f, 0.f, 0.f, 0.f);

    int j = s;
    for (; j + 3 < e; j += 4) {
        const float4* r[4];
#pragma unroll
        for (int u = 0; u < 4; u++) r[u] = (const float4*)(X + (size_t)col[j + u] * F);
#pragma unroll
        for (int v = 0; v < NV; v++) {
            float4 t[4];
#pragma unroll
            for (int u = 0; u < 4; u++) t[u] = __ldg(&r[u][lane + 32 * v]);
#pragma unroll
            for (int u = 0; u < 4; u++) {
                acc[u][v].x += t[u].x; acc[u][v].y += t[u].y;
                acc[u][v].z += t[u].z; acc[u][v].w += t[u].w;
            }
        }
    }
    for (; j < e; j++) {
        const float4* r0 = (const float4*)(X + (size_t)col[j] * F);
#pragma unroll
        for (int v = 0; v < NV; v++) {
            float4 t0 = __ldg(&r0[lane + 32 * v]);
            acc[0][v].x += t0.x; acc[0][v].y += t0.y;
            acc[0][v].z += t0.z; acc[0][v].w += t0.w;
        }
    }
    float inv = (e > s) ? 1.0f / (float)(e - s) : 0.0f;
    float4* o = (float4*)(out + (size_t)w * F);
#pragma unroll
    for (int v = 0; v < NV; v++) {
        float4 t;
        t.x = (acc[0][v].x + acc[1][v].x + acc[2][v].x + acc[3][v].x) * inv;
        t.y = (acc[0][v].y + acc[1][v].y + acc[2][v].y + acc[3][v].y) * inv;
        t.z = (acc[0][v].z + acc[1][v].z + acc[2][v].z + acc[3][v].z) * inv;
        t.w = (acc[0][v].w + acc[1][v].w + acc[2][v].w + acc[3][v].w) * inv;
        o[lane + 32 * v] = t;
    }
}

__global__ __launch_bounds__(256) void agg_mean_64(const float* __restrict__ X,
                                                   const int* __restrict__ rs,
                                                   const int* __restrict__ col,
                                                   float* __restrict__ out, int ndst) {
    int w = blockIdx.x * 8 + (threadIdx.x >> 5);
    int lane = threadIdx.x & 31;
    if (w >= ndst) return;
    int s = rs[w], e = rs[w + 1];
    float2 acc[4];
#pragma unroll
    for (int u = 0; u < 4; u++) acc[u] = make_float2(0.f, 0.f);
    int j = s;
    for (; j + 3 < e; j += 4) {
        float2 t[4];
#pragma unroll
        for (int u = 0; u < 4; u++)
            t[u] = __ldg((const float2*)(X + (size_t)col[j + u] * 64) + lane);
#pragma unroll
        for (int u = 0; u < 4; u++) { acc[u].x += t[u].x; acc[u].y += t[u].y; }
    }
    for (; j < e; j++) {
        float2 t0 = __ldg((const float2*)(X + (size_t)col[j] * 64) + lane);
        acc[0].x += t0.x; acc[0].y += t0.y;
    }
    float inv = (e > s) ? 1.0f / (float)(e - s) : 0.0f;
    float2 t = make_float2((acc[0].x + acc[1].x + acc[2].x + acc[3].x) * inv,
                           (acc[0].y + acc[1].y + acc[2].y + acc[3].y) * inv);
    ((float2*)(out + (size_t)w * 64))[lane] = t;
}

// ================= tf32 mma.sync dual-A GEMM =================
// C[M,256] = act(A1[M,K1] @ W1[256,K1]^T + A2[M,K2] @ W2[256,K2]^T + bias)
// CTA tile: 128x128 (grid.y = 2 covers N=256). BK=32, 2-stage SMEM ping-pong.
// 8 warps, 2x4 grid, warp tile 64x32, mma.m16n8k8.tf32. 2 CTAs/SM.

#define GEMM_BK     32
#define A_STAGE_B   16384                  // 128 x 32 f32
#define B_STAGE_B   16384                  // 128 x 32 f32
#define STAGE_B     (A_STAGE_B + B_STAGE_B)
#define GEMM_SMEM   (2 * STAGE_B)          // 64 KB dynamic

__device__ __forceinline__ uint32_t f2tf32(float x) {
    uint32_t r;
    asm("cvt.rna.tf32.f32 %0, %1;" : "=r"(r) : "f"(x));
    return r;
}

__device__ __forceinline__ uint32_t smem_u32(const void* p) {
    uint32_t a;
    asm("{ .reg .u64 t; cvta.to.shared.u64 t, %1; cvt.u32.u64 %0, t; }" : "=r"(a) : "l"(p));
    return a;
}

__device__ __forceinline__ void mma_tf32(float* d, const uint32_t* a, const uint32_t* b) {
    asm volatile(
        "mma.sync.aligned.m16n8k8.row.col.f32.tf32.tf32.f32 "
        "{%0,%1,%2,%3}, {%4,%5,%6,%7}, {%8,%9}, {%0,%1,%2,%3};"
        : "+f"(d[0]), "+f"(d[1]), "+f"(d[2]), "+f"(d[3])
        : "r"(a[0]), "r"(a[1]), "r"(a[2]), "r"(a[3]), "r"(b[0]), "r"(b[1]));
}

__device__ __forceinline__ void sts32(uint32_t addr, uint32_t v) {
    asm volatile("st.shared.b32 [%0], %1;" :: "r"(addr), "r"(v) : "memory");
}
__device__ __forceinline__ void lds128(uint32_t* r, uint32_t addr) {
    asm volatile("ld.shared.v4.b32 {%0,%1,%2,%3}, [%4];"
                 : "=r"(r[0]), "=r"(r[1]), "=r"(r[2]), "=r"(r[3]) : "r"(addr) : "memory");
}
__device__ __forceinline__ void lds64(uint32_t* r, uint32_t addr) {
    asm volatile("ld.shared.v2.b32 {%0,%1}, [%2];"
                 : "=r"(r[0]), "=r"(r[1]) : "r"(addr) : "memory");
}

template <bool RELU>
__global__ __launch_bounds__(256, 2) void gemm_mma_kernel(
    const float* __restrict__ A1, int K1, const float* __restrict__ W1,
    const float* __restrict__ A2, int K2, const float* __restrict__ W2,
    const float* __restrict__ bias, float* __restrict__ C, int M) {
    extern __shared__ __align__(16) char dsmem[];
    const uint32_t smem = smem_u32(dsmem);

    const int tid = threadIdx.x;
    const int wid = tid >> 5;
    const int lane = tid & 31;
    const int warp_m = wid >> 2;   // 0..1 (64 rows each)
    const int warp_n = wid & 3;    // 0..3 (32 cols each)
    const int m0 = blockIdx.x * 128;
    const int n0 = blockIdx.y * 128;

    // ---- writer-side precomputed offsets ----
    const int r0 = tid >> 3;       // base row 0..31 (row_q = r0 + 32q)
    const int c4 = tid & 7;        // float4 column within BK (fixed across q)
    const int wks = c4 >> 1;
    const int wkh = c4 & 1;
    // A store: block (mt*4+ks), lane (g8*4+j), reg ri = wkh*2 + rhalf
    const uint32_t aoff0 = (uint32_t)(((((r0 >> 4) * 4 + wks) * 32) + (r0 & 7) * 4) * 16
                                      + (wkh * 2 + ((r0 >> 3) & 1)) * 4);
    // B store: block (nt*4+ks), lane (g*4+j), reg ri = wkh
    const uint32_t boff0 = (uint32_t)(((((r0 >> 3) * 4 + wks) * 32) + (r0 & 7) * 4) * 8
                                      + wkh * 4);

    float acc[4][4][4];
#pragma unroll
    for (int i = 0; i < 4; i++)
#pragma unroll
        for (int j = 0; j < 4; j++)
#pragma unroll
            for (int k = 0; k < 4; k++) acc[i][j][k] = 0.f;

    const int n1 = K1 / GEMM_BK;
    const int n2 = K2 / GEMM_BK;
    const int T = n1 + n2;

    float4 aR[4], bR[4];

    // ---- global load of iteration `it` into registers ----
    auto load_g = [&](int it) {
        const float* A; const float* W; int K, k0;
        if (it < n1) { A = A1; W = W1; K = K1; k0 = it * GEMM_BK; }
        else         { A = A2; W = W2; K = K2; k0 = (it - n1) * GEMM_BK; }
        const int cc = k0 + c4 * 4;
#pragma unroll
        for (int q = 0; q < 4; q++) {
            const int row = r0 + 32 * q;
            aR[q] = (m0 + row < M)
                  ? *(const float4*)(A + (size_t)(m0 + row) * K + cc)
                  : make_float4(0.f, 0.f, 0.f, 0.f);
            bR[q] = *(const float4*)(W + (size_t)(n0 + row) * K + cc);
        }
    };

    // ---- store staged registers to SMEM stage s (tf32-rounded, permuted) ----
    auto store_s = [&](int s) {
        const uint32_t sA = smem + s * STAGE_B;
        const uint32_t sB = sA + A_STAGE_B;
#pragma unroll
        for (int q = 0; q < 4; q++) {
            const uint32_t a0 = sA + aoff0 + 4096u * q;
            sts32(a0 +  0, f2tf32(aR[q].x));
            sts32(a0 + 16, f2tf32(aR[q].y));
            sts32(a0 + 32, f2tf32(aR[q].z));
            sts32(a0 + 48, f2tf32(aR[q].w));
            const uint32_t b0 = sB + boff0 + 4096u * q;
            sts32(b0 +  0, f2tf32(bR[q].x));
            sts32(b0 +  8, f2tf32(bR[q].y));
            sts32(b0 + 16, f2tf32(bR[q].z));
            sts32(b0 + 24, f2tf32(bR[q].w));
        }
    };

    // ---- compute one BK stage from SMEM ----
    auto compute_s = [&](int s) {
        const uint32_t sA = smem + s * STAGE_B;
        const uint32_t sB = sA + A_STAGE_B;
#pragma unroll
        for (int ks = 0; ks < 4; ks++) {
            uint32_t af[4][4], bf[4][2];
#pragma unroll
            for (int i = 0; i < 4; i++)
                lds128(af[i], sA + (uint32_t)((((warp_m * 4 + i) * 4 + ks) * 32 + lane) * 16));
#pragma unroll
            for (int j = 0; j < 4; j++)
                lds64(bf[j], sB + (uint32_t)((((warp_n * 4 + j) * 4 + ks) * 32 + lane) * 8));
#pragma unroll
            for (int i = 0; i < 4; i++)
#pragma unroll
                for (int j = 0; j < 4; j++)
                    mma_tf32(acc[i][j], af[i], bf[j]);
        }
    };

    // ---- pipelined main loop ----
    load_g(0);
    store_s(0);
    __syncthreads();
    int s = 0;
#pragma unroll 1
    for (int it = 0; it < T; it++) {
        if (it + 1 < T) load_g(it + 1);
        compute_s(s);
        if (it + 1 < T) store_s(1 - s);
        __syncthreads();
        s ^= 1;
    }

    // ---- epilogue: bias (+relu), direct global store ----
    const int g = lane >> 2;
    const int t = lane & 3;
#pragma unroll
    for (int j = 0; j < 4; j++) {
        const int nb = n0 + warp_n * 32 + j * 8 + t * 2;
        const float bx = bias[nb], by = bias[nb + 1];
#pragma unroll
        for (int i = 0; i < 4; i++) {
            const int rlo = m0 + warp_m * 64 + i * 16 + g;
            if (rlo < M) {
                float2 v = make_float2(acc[i][j][0] + bx, acc[i][j][1] + by);
                if (RELU) { v.x = fmaxf(v.x, 0.f); v.y = fmaxf(v.y, 0.f); }
                *(float2*)(C + (size_t)rlo * HH + nb) = v;
            }
            const int rhi = rlo + 8;
            if (rhi < M) {
                float2 v = make_float2(acc[i][j][2] + bx, acc[i][j][3] + by);
                if (RELU) { v.x = fmaxf(v.x, 0.f); v.y = fmaxf(v.y, 0.f); }
                *(float2*)(C + (size_t)rhi * HH + nb) = v;
            }
        }
    }
}

// ---------------- host ----------------
extern "C" void kernel_launch(void* const* d_in, const int* in_sizes, int n_in,
                              void* d_out, int out_size) {
    const float* x_user = (const float*)d_in[0];
    const float* x_item = (const float*)d_in[1];
    const int* ui_src = (const int*)d_in[2];
    const int* ui_dst = (const int*)d_in[3];
    const int* iu_src = (const int*)d_in[4];
    const int* iu_dst = (const int*)d_in[5];
    const float* W1l_ui = (const float*)d_in[6];
    const float* b1_ui  = (const float*)d_in[7];
    const float* W1r_ui = (const float*)d_in[8];
    const float* W1l_iu = (const float*)d_in[9];
    const float* b1_iu  = (const float*)d_in[10];
    const float* W1r_iu = (const float*)d_in[11];
    const float* W2l_ui = (const float*)d_in[12];
    const float* b2_ui  = (const float*)d_in[13];
    const float* W2r_ui = (const float*)d_in[14];
    const float* W2l_iu = (const float*)d_in[15];
    const float* b2_iu  = (const float*)d_in[16];
    const float* W2r_iu = (const float*)d_in[17];

    int *cnt_item, *cnt_user, *cur_item, *cur_user, *rs_item, *rs_user, *col_ui, *col_iu;
    float *agg_item, *agg_user, *h_item, *h_user, *aggH_item, *aggH_user;
    cudaGetSymbolAddress((void**)&cnt_item, g_cnt_item);
    cudaGetSymbolAddress((void**)&cnt_user, g_cnt_user);
    cudaGetSymbolAddress((void**)&cur_item, g_cur_item);
    cudaGetSymbolAddress((void**)&cur_user, g_cur_user);
    cudaGetSymbolAddress((void**)&rs_item, g_rs_item);
    cudaGetSymbolAddress((void**)&rs_user, g_rs_user);
    cudaGetSymbolAddress((void**)&col_ui, g_col_ui);
    cudaGetSymbolAddress((void**)&col_iu, g_col_iu);
    cudaGetSymbolAddress((void**)&agg_item, g_agg_item);
    cudaGetSymbolAddress((void**)&agg_user, g_agg_user);
    cudaGetSymbolAddress((void**)&h_item, g_h_item);
    cudaGetSymbolAddress((void**)&h_user, g_h_user);
    cudaGetSymbolAddress((void**)&aggH_item, g_aggH_item);
    cudaGetSymbolAddress((void**)&aggH_user, g_aggH_user);

    cudaFuncSetAttribute(gemm_mma_kernel<true>,
                         cudaFuncAttributeMaxDynamicSharedMemorySize, GEMM_SMEM);
    cudaFuncSetAttribute(gemm_mma_kernel<false>,
                         cudaFuncAttributeMaxDynamicSharedMemorySize, GEMM_SMEM);

    cudaMemsetAsync(cnt_item, 0, N_ITEMC * sizeof(int), 0);
    cudaMemsetAsync(cnt_user, 0, N_USERC * sizeof(int), 0);
    cudaMemsetAsync(cur_item, 0, N_ITEMC * sizeof(int), 0);
    cudaMemsetAsync(cur_user, 0, N_USERC * sizeof(int), 0);

    // CSR build (reused by both layers)
    count_kernel<<<(NE + 255) / 256, 256>>>(ui_dst, iu_dst);
    scan_kernel<<<2, 1024>>>();
    fill_kernel<<<(NE + 255) / 256, 256>>>(ui_src, ui_dst, iu_src, iu_dst);

    // layer 1 aggregation
    agg_mean_v4<1><<<(N_ITEMC + 7) / 8, 256>>>(x_user, rs_item, col_ui, agg_item, N_ITEMC);
    agg_mean_64<<<(N_USERC + 7) / 8, 256>>>(x_item, rs_user, col_iu, agg_user, N_USERC);

    // layer 1 fused GEMM + bias + relu (tf32 tensor cores)
    gemm_mma_kernel<true><<<dim3((N_ITEMC + 127) / 128, 2), 256, GEMM_SMEM>>>(
        agg_item, DU, W1l_ui, x_item, DI, W1r_ui, b1_ui, h_item, N_ITEMC);
    gemm_mma_kernel<true><<<dim3((N_USERC + 127) / 128, 2), 256, GEMM_SMEM>>>(
        agg_user, DI, W1l_iu, x_user, DU, W1r_iu, b1_iu, h_user, N_USERC);

    // layer 2 aggregation (H = 256)
    agg_mean_v4<2><<<(N_ITEMC + 7) / 8, 256>>>(h_user, rs_item, col_ui, aggH_item, N_ITEMC);
    agg_mean_v4<2><<<(N_USERC + 7) / 8, 256>>>(h_item, rs_user, col_iu, aggH_user, N_USERC);

    // layer 2 fused GEMM + bias (output order: out_user then out_item)
    float* out_user = (float*)d_out;
    float* out_item = out_user + (size_t)N_USERC * HH;
    gemm_mma_kernel<false><<<dim3((N_ITEMC + 127) / 128, 2), 256, GEMM_SMEM>>>(
        aggH_item, HH, W2l_ui, h_item, HH, W2r_ui, b2_ui, out_item, N_ITEMC);
    gemm_mma_kernel<false><<<dim3((N_USERC + 127) / 128, 2), 256, GEMM_SMEM>>>(
        aggH_user, HH, W2l_iu, h_user, HH, W2r_iu, b2_iu, out_user, N_USERC);
}

// round 7
// speedup vs baseline: 2.1394x; 1.1311x over previous
#include <cuda_runtime.h>
#include <cstdint>

#define N_USERC 100000
#define N_ITEMC 50000
#define NE      1600000
#define DU      128
#define DI      64
#define HH      256

#define NBLK_ITEM ((N_ITEMC + 6249) / 6250 ? (N_ITEMC + 7) / 8 / 782 : 0) /* unused */
#define AGG_BLK_ITEM ((N_ITEMC + 7) / 8)     // 6250
#define AGG_BLK_USER ((N_USERC + 7) / 8)     // 12500
#define MBLK_ITEM ((N_ITEMC + 127) / 128)    // 391
#define MBLK_USER ((N_USERC + 127) / 128)    // 782

// ---------------- device scratch (no runtime allocation allowed) ----------------
__device__ int g_cnt_item[N_ITEMC];
__device__ int g_cnt_user[N_USERC];
__device__ int g_cur_item[N_ITEMC];
__device__ int g_cur_user[N_USERC];
__device__ int g_rs_item[N_ITEMC + 1];
__device__ int g_rs_user[N_USERC + 1];
__device__ int g_col_ui[NE];
__device__ int g_col_iu[NE];

__device__ unsigned int g_tkt[2];
__device__ unsigned long long g_desc[2][160];

__device__ float g_agg_item[(size_t)N_ITEMC * DU];
__device__ float g_agg_user[(size_t)N_USERC * DI];
__device__ float g_h_item[(size_t)N_ITEMC * HH];
__device__ float g_h_user[(size_t)N_USERC * HH];
__device__ float g_aggH_item[(size_t)N_ITEMC * HH];
__device__ float g_aggH_user[(size_t)N_USERC * HH];

// ---------------- CSR build ----------------
__global__ void count_kernel(const int* __restrict__ ui_dst, const int* __restrict__ iu_dst) {
    int i = blockIdx.x * blockDim.x + threadIdx.x;
    if (i < NE) {
        atomicAdd(&g_cnt_item[ui_dst[i]], 1);
        atomicAdd(&g_cnt_user[iu_dst[i]], 1);
    }
}

// Single-pass decoupled-lookback exclusive scan; also zeroes cur arrays.
// grid = (98, 2), 256 threads; 1024 elems per block.
__global__ void scan_lookback_kernel() {
    const int y = blockIdx.y;
    const int* __restrict__ cnt = y == 0 ? g_cnt_item : g_cnt_user;
    int* __restrict__ rs  = y == 0 ? g_rs_item  : g_rs_user;
    int* __restrict__ cur = y == 0 ? g_cur_item : g_cur_user;
    const int n = y == 0 ? N_ITEMC : N_USERC;
    const int nblk = (n + 1023) / 1024;
    if (blockIdx.x >= nblk) return;

    __shared__ int s_vb;
    __shared__ int s_wsum[8];
    __shared__ int s_run;
    const int tid = threadIdx.x, lane = tid & 31, wid = tid >> 5;

    if (tid == 0) s_vb = atomicAdd(&g_tkt[y], 1u);
    __syncthreads();
    const int vb = s_vb;
    const int base = vb * 1024 + tid * 4;

    int v0 = 0, v1 = 0, v2 = 0, v3 = 0;
    if (base + 3 < n) {
        v0 = cnt[base]; v1 = cnt[base + 1]; v2 = cnt[base + 2]; v3 = cnt[base + 3];
    } else {
        if (base     < n) v0 = cnt[base];
        if (base + 1 < n) v1 = cnt[base + 1];
        if (base + 2 < n) v2 = cnt[base + 2];
        if (base + 3 < n) v3 = cnt[base + 3];
    }
    const int tot = v0 + v1 + v2 + v3;
    int inc = tot;
#pragma unroll
    for (int o = 1; o < 32; o <<= 1) {
        int u = __shfl_up_sync(0xffffffffu, inc, o);
        if (lane >= o) inc += u;
    }
    if (lane == 31) s_wsum[wid] = inc;
    __syncthreads();
    if (wid == 0) {
        int w = (lane < 8) ? s_wsum[lane] : 0;
#pragma unroll
        for (int o = 1; o < 8; o <<= 1) {
            int u = __shfl_up_sync(0xffffffffu, w, o);
            if (lane >= o) w += u;
        }
        if (lane < 8) s_wsum[lane] = w;
    }
    __syncthreads();
    const int agg = s_wsum[7];
    const int thr_exc = (wid ? s_wsum[wid - 1] : 0) + inc - tot;

    if (tid == 0) {
        if (vb == 0) {
            atomicExch(&g_desc[y][0], (2ull << 32) | (unsigned)agg);
            s_run = 0;
        } else {
            atomicExch(&g_desc[y][vb], (1ull << 32) | (unsigned)agg);
            int run = 0, p = vb - 1;
            while (true) {
                unsigned long long d;
                do { d = atomicAdd(&g_desc[y][p], 0ull); } while ((d >> 32) == 0ull);
                run += (int)(d & 0xffffffffull);
                if ((d >> 32) == 2ull) break;
                p--;
            }
            atomicExch(&g_desc[y][vb], (2ull << 32) | (unsigned)(run + agg));
            s_run = run;
        }
    }
    __syncthreads();
    const int run = s_run;
    const int e0 = run + thr_exc;
    if (base     < n) { rs[base]     = e0;                cur[base]     = 0; }
    if (base + 1 < n) { rs[base + 1] = e0 + v0;           cur[base + 1] = 0; }
    if (base + 2 < n) { rs[base + 2] = e0 + v0 + v1;      cur[base + 2] = 0; }
    if (base + 3 < n) { rs[base + 3] = e0 + v0 + v1 + v2; cur[base + 3] = 0; }
    if (vb == nblk - 1 && tid == 0) rs[n] = run + agg;
}

__global__ void fill_kernel(const int* __restrict__ ui_src, const int* __restrict__ ui_dst,
                            const int* __restrict__ iu_src, const int* __restrict__ iu_dst) {
    int i = blockIdx.x * blockDim.x + threadIdx.x;
    if (i >= NE) return;
    {
        int d = ui_dst[i];
        int p = atomicAdd(&g_cur_item[d], 1);
        g_col_ui[g_rs_item[d] + p] = ui_src[i];
    }
    {
        int d = iu_dst[i];
        int p = atomicAdd(&g_cur_user[d], 1);
        g_col_iu[g_rs_user[d] + p] = iu_src[i];
    }
}

// ---------------- gather-based segment mean bodies ----------------
template <int NV>
__device__ __forceinline__ void agg_body_v4(const float* __restrict__ X,
                                            const int* __restrict__ rs,
                                            const int* __restrict__ col,
                                            float* __restrict__ out, int w, int lane) {
    int s = rs[w], e = rs[w + 1];
    constexpr int F = NV * 128;

    float4 acc[4][NV];
#pragma unroll
    for (int u = 0; u < 4; u++)
#pragma unroll
        for (int v = 0; v < NV; v++) acc[u][v] = make_float4(0.f, 0.f, 0.f, 0.f);

    int j = s;
    for (; j + 3 < e; j += 4) {
        const float4* r[4];
#pragma unroll
        for (int u = 0; u < 4; u++) r[u] = (const float4*)(X + (size_t)col[j + u] * F);
#pragma unroll
        for (int v = 0; v < NV; v++) {
            float4 t[4];
#pragma unroll
            for (int u = 0; u < 4; u++) t[u] = __ldg(&r[u][lane + 32 * v]);
#pragma unroll
            for (int u = 0; u < 4; u++) {
                acc[u][v].x += t[u].x; acc[u][v].y += t[u].y;
                acc[u][v].z += t[u].z; acc[u][v].w += t[u].w;
            }
        }
    }
    for (; j < e; j++) {
        const float4* r0 = (const float4*)(X + (size_t)col[j] * F);
#pragma unroll
        for (int v = 0; v < NV; v++) {
            float4 t0 = __ldg(&r0[lane + 32 * v]);
            acc[0][v].x += t0.x; acc[0][v].y += t0.y;
            acc[0][v].z += t0.z; acc[0][v].w += t0.w;
        }
    }
    float inv = (e > s) ? 1.0f / (float)(e - s) : 0.0f;
    float4* o = (float4*)(out + (size_t)w * F);
#pragma unroll
    for (int v = 0; v < NV; v++) {
        float4 t;
        t.x = (acc[0][v].x + acc[1][v].x + acc[2][v].x + acc[3][v].x) * inv;
        t.y = (acc[0][v].y + acc[1][v].y + acc[2][v].y + acc[3][v].y) * inv;
        t.z = (acc[0][v].z + acc[1][v].z + acc[2][v].z + acc[3][v].z) * inv;
        t.w = (acc[0][v].w + acc[1][v].w + acc[2][v].w + acc[3][v].w) * inv;
        o[lane + 32 * v] = t;
    }
}

__device__ __forceinline__ void agg_body_64(const float* __restrict__ X,
                                            const int* __restrict__ rs,
                                            const int* __restrict__ col,
                                            float* __restrict__ out, int w, int lane) {
    int s = rs[w], e = rs[w + 1];
    float2 acc[4];
#pragma unroll
    for (int u = 0; u < 4; u++) acc[u] = make_float2(0.f, 0.f);
    int j = s;
    for (; j + 3 < e; j += 4) {
        float2 t[4];
#pragma unroll
        for (int u = 0; u < 4; u++)
            t[u] = __ldg((const float2*)(X + (size_t)col[j + u] * 64) + lane);
#pragma unroll
        for (int u = 0; u < 4; u++) { acc[u].x += t[u].x; acc[u].y += t[u].y; }
    }
    for (; j < e; j++) {
        float2 t0 = __ldg((const float2*)(X + (size_t)col[j] * 64) + lane);
        acc[0].x += t0.x; acc[0].y += t0.y;
    }
    float inv = (e > s) ? 1.0f / (float)(e - s) : 0.0f;
    float2 t = make_float2((acc[0].x + acc[1].x + acc[2].x + acc[3].x) * inv,
                           (acc[0].y + acc[1].y + acc[2].y + acc[3].y) * inv);
    ((float2*)(out + (size_t)w * 64))[lane] = t;
}

// Fused layer-1 aggregation: blocks [0,6250) item (F=128), [6250,18750) user (F=64)
__global__ __launch_bounds__(256) void agg_l1_kernel(const float* __restrict__ x_user,
                                                     const float* __restrict__ x_item) {
    const int gb = blockIdx.x;
    const int lane = threadIdx.x & 31;
    const int wl = threadIdx.x >> 5;
    if (gb < AGG_BLK_ITEM) {
        int w = gb * 8 + wl;
        if (w < N_ITEMC) agg_body_v4<1>(x_user, g_rs_item, g_col_ui, g_agg_item, w, lane);
    } else {
        int w = (gb - AGG_BLK_ITEM) * 8 + wl;
        if (w < N_USERC) agg_body_64(x_item, g_rs_user, g_col_iu, g_agg_user, w, lane);
    }
}

// Fused layer-2 aggregation: both F=256
__global__ __launch_bounds__(256) void agg_l2_kernel() {
    const int gb = blockIdx.x;
    const int lane = threadIdx.x & 31;
    const int wl = threadIdx.x >> 5;
    if (gb < AGG_BLK_ITEM) {
        int w = gb * 8 + wl;
        if (w < N_ITEMC) agg_body_v4<2>(g_h_user, g_rs_item, g_col_ui, g_aggH_item, w, lane);
    } else {
        int w = (gb - AGG_BLK_ITEM) * 8 + wl;
        if (w < N_USERC) agg_body_v4<2>(g_h_item, g_rs_user, g_col_iu, g_aggH_user, w, lane);
    }
}

// ================= tf32 mma.sync dual-A GEMM (fused item+user) =================
#define GEMM_BK     32
#define A_STAGE_B   16384
#define B_STAGE_B   16384
#define STAGE_B     (A_STAGE_B + B_STAGE_B)
#define GEMM_SMEM   (2 * STAGE_B)          // 64 KB dynamic

struct GemmSide {
    const float* A1; const float* W1;
    const float* A2; const float* W2;
    const float* bias; float* C;
    int K1; int K2; int M;
};

__device__ __forceinline__ uint32_t f2tf32(float x) {
    uint32_t r;
    asm("cvt.rna.tf32.f32 %0, %1;" : "=r"(r) : "f"(x));
    return r;
}

__device__ __forceinline__ uint32_t smem_u32(const void* p) {
    uint32_t a;
    asm("{ .reg .u64 t; cvta.to.shared.u64 t, %1; cvt.u32.u64 %0, t; }" : "=r"(a) : "l"(p));
    return a;
}

__device__ __forceinline__ void mma_tf32(float* d, const uint32_t* a, const uint32_t* b) {
    asm volatile(
        "mma.sync.aligned.m16n8k8.row.col.f32.tf32.tf32.f32 "
        "{%0,%1,%2,%3}, {%4,%5,%6,%7}, {%8,%9}, {%0,%1,%2,%3};"
        : "+f"(d[0]), "+f"(d[1]), "+f"(d[2]), "+f"(d[3])
        : "r"(a[0]), "r"(a[1]), "r"(a[2]), "r"(a[3]), "r"(b[0]), "r"(b[1]));
}

__device__ __forceinline__ void sts32(uint32_t addr, uint32_t v) {
    asm volatile("st.shared.b32 [%0], %1;" :: "r"(addr), "r"(v) : "memory");
}
__device__ __forceinline__ void lds128(uint32_t* r, uint32_t addr) {
    asm volatile("ld.shared.v4.b32 {%0,%1,%2,%3}, [%4];"
                 : "=r"(r[0]), "=r"(r[1]), "=r"(r[2]), "=r"(r[3]) : "r"(addr) : "memory");
}
__device__ __forceinline__ void lds64(uint32_t* r, uint32_t addr) {
    asm volatile("ld.shared.v2.b32 {%0,%1}, [%2];"
                 : "=r"(r[0]), "=r"(r[1]) : "r"(addr) : "memory");
}

template <bool RELU>
__global__ __launch_bounds__(256, 2) void gemm_mma_fused(GemmSide sa, GemmSide sb, int mblk_a) {
    extern __shared__ __align__(16) char dsmem[];
    const uint32_t smem = smem_u32(dsmem);

    const bool sideA = (int)blockIdx.x < mblk_a;
    const float* A1 = sideA ? sa.A1 : sb.A1;
    const float* W1 = sideA ? sa.W1 : sb.W1;
    const float* A2 = sideA ? sa.A2 : sb.A2;
    const float* W2 = sideA ? sa.W2 : sb.W2;
    const float* bias = sideA ? sa.bias : sb.bias;
    float* C = sideA ? sa.C : sb.C;
    const int K1 = sideA ? sa.K1 : sb.K1;
    const int K2 = sideA ? sa.K2 : sb.K2;
    const int M  = sideA ? sa.M  : sb.M;
    const int mb = sideA ? blockIdx.x : blockIdx.x - mblk_a;

    const int tid = threadIdx.x;
    const int wid = tid >> 5;
    const int lane = tid & 31;
    const int warp_m = wid >> 2;   // 0..1
    const int warp_n = wid & 3;    // 0..3
    const int m0 = mb * 128;
    const int n0 = blockIdx.y * 128;

    const int r0 = tid >> 3;
    const int c4 = tid & 7;
    const int wks = c4 >> 1;
    const int wkh = c4 & 1;
    const uint32_t aoff0 = (uint32_t)(((((r0 >> 4) * 4 + wks) * 32) + (r0 & 7) * 4) * 16
                                      + (wkh * 2 + ((r0 >> 3) & 1)) * 4);
    const uint32_t boff0 = (uint32_t)(((((r0 >> 3) * 4 + wks) * 32) + (r0 & 7) * 4) * 8
                                      + wkh * 4);

    float acc[4][4][4];
#pragma unroll
    for (int i = 0; i < 4; i++)
#pragma unroll
        for (int j = 0; j < 4; j++)
#pragma unroll
            for (int k = 0; k < 4; k++) acc[i][j][k] = 0.f;

    const int n1 = K1 / GEMM_BK;
    const int n2 = K2 / GEMM_BK;
    const int T = n1 + n2;

    float4 aR[4], bR[4];

    auto load_g = [&](int it) {
        const float* A; const float* W; int K, k0;
        if (it < n1) { A = A1; W = W1; K = K1; k0 = it * GEMM_BK; }
        else         { A = A2; W = W2; K = K2; k0 = (it - n1) * GEMM_BK; }
        const int cc = k0 + c4 * 4;
#pragma unroll
        for (int q = 0; q < 4; q++) {
            const int row = r0 + 32 * q;
            aR[q] = (m0 + row < M)
                  ? *(const float4*)(A + (size_t)(m0 + row) * K + cc)
                  : make_float4(0.f, 0.f, 0.f, 0.f);
            bR[q] = *(const float4*)(W + (size_t)(n0 + row) * K + cc);
        }
    };

    auto store_s = [&](int s) {
        const uint32_t sA = smem + s * STAGE_B;
        const uint32_t sB = sA + A_STAGE_B;
#pragma unroll
        for (int q = 0; q < 4; q++) {
            const uint32_t a0 = sA + aoff0 + 4096u * q;
            sts32(a0 +  0, f2tf32(aR[q].x));
            sts32(a0 + 16, f2tf32(aR[q].y));
            sts32(a0 + 32, f2tf32(aR[q].z));
            sts32(a0 + 48, f2tf32(aR[q].w));
            const uint32_t b0 = sB + boff0 + 4096u * q;
            sts32(b0 +  0, f2tf32(bR[q].x));
            sts32(b0 +  8, f2tf32(bR[q].y));
            sts32(b0 + 16, f2tf32(bR[q].z));
            sts32(b0 + 24, f2tf32(bR[q].w));
        }
    };

    auto compute_s = [&](int s) {
        const uint32_t sA = smem + s * STAGE_B;
        const uint32_t sB = sA + A_STAGE_B;
#pragma unroll
        for (int ks = 0; ks < 4; ks++) {
            uint32_t af[4][4], bf[4][2];
#pragma unroll
            for (int i = 0; i < 4; i++)
                lds128(af[i], sA + (uint32_t)((((warp_m * 4 + i) * 4 + ks) * 32 + lane) * 16));
#pragma unroll
            for (int j = 0; j < 4; j++)
                lds64(bf[j], sB + (uint32_t)((((warp_n * 4 + j) * 4 + ks) * 32 + lane) * 8));
#pragma unroll
            for (int i = 0; i < 4; i++)
#pragma unroll
                for (int j = 0; j < 4; j++)
                    mma_tf32(acc[i][j], af[i], bf[j]);
        }
    };

    load_g(0);
    store_s(0);
    __syncthreads();
    int s = 0;
#pragma unroll 1
    for (int it = 0; it < T; it++) {
        if (it + 1 < T) load_g(it + 1);
        compute_s(s);
        if (it + 1 < T) store_s(1 - s);
        __syncthreads();
        s ^= 1;
    }

    const int g = lane >> 2;
    const int t = lane & 3;
#pragma unroll
    for (int j = 0; j < 4; j++) {
        const int nb = n0 + warp_n * 32 + j * 8 + t * 2;
        const float bx = bias[nb], by = bias[nb + 1];
#pragma unroll
        for (int i = 0; i < 4; i++) {
            const int rlo = m0 + warp_m * 64 + i * 16 + g;
            if (rlo < M) {
                float2 v = make_float2(acc[i][j][0] + bx, acc[i][j][1] + by);
                if (RELU) { v.x = fmaxf(v.x, 0.f); v.y = fmaxf(v.y, 0.f); }
                *(float2*)(C + (size_t)rlo * HH + nb) = v;
            }
            const int rhi = rlo + 8;
            if (rhi < M) {
                float2 v = make_float2(acc[i][j][2] + bx, acc[i][j][3] + by);
                if (RELU) { v.x = fmaxf(v.x, 0.f); v.y = fmaxf(v.y, 0.f); }
                *(float2*)(C + (size_t)rhi * HH + nb) = v;
            }
        }
    }
}

// ---------------- host ----------------
extern "C" void kernel_launch(void* const* d_in, const int* in_sizes, int n_in,
                              void* d_out, int out_size) {
    const float* x_user = (const float*)d_in[0];
    const float* x_item = (const float*)d_in[1];
    const int* ui_src = (const int*)d_in[2];
    const int* ui_dst = (const int*)d_in[3];
    const int* iu_src = (const int*)d_in[4];
    const int* iu_dst = (const int*)d_in[5];
    const float* W1l_ui = (const float*)d_in[6];
    const float* b1_ui  = (const float*)d_in[7];
    const float* W1r_ui = (const float*)d_in[8];
    const float* W1l_iu = (const float*)d_in[9];
    const float* b1_iu  = (const float*)d_in[10];
    const float* W1r_iu = (const float*)d_in[11];
    const float* W2l_ui = (const float*)d_in[12];
    const float* b2_ui  = (const float*)d_in[13];
    const float* W2r_ui = (const float*)d_in[14];
    const float* W2l_iu = (const float*)d_in[15];
    const float* b2_iu  = (const float*)d_in[16];
    const float* W2r_iu = (const float*)d_in[17];

    int *cnt_item, *cnt_user;
    unsigned int* tkt;
    unsigned long long* desc;
    float *agg_item, *agg_user, *h_item, *h_user, *aggH_item, *aggH_user;
    cudaGetSymbolAddress((void**)&cnt_item, g_cnt_item);
    cudaGetSymbolAddress((void**)&cnt_user, g_cnt_user);
    cudaGetSymbolAddress((void**)&tkt, g_tkt);
    cudaGetSymbolAddress((void**)&desc, g_desc);
    cudaGetSymbolAddress((void**)&agg_item, g_agg_item);
    cudaGetSymbolAddress((void**)&agg_user, g_agg_user);
    cudaGetSymbolAddress((void**)&h_item, g_h_item);
    cudaGetSymbolAddress((void**)&h_user, g_h_user);
    cudaGetSymbolAddress((void**)&aggH_item, g_aggH_item);
    cudaGetSymbolAddress((void**)&aggH_user, g_aggH_user);

    cudaFuncSetAttribute(gemm_mma_fused<true>,
                         cudaFuncAttributeMaxDynamicSharedMemorySize, GEMM_SMEM);
    cudaFuncSetAttribute(gemm_mma_fused<false>,
                         cudaFuncAttributeMaxDynamicSharedMemorySize, GEMM_SMEM);

    cudaMemsetAsync(cnt_item, 0, N_ITEMC * sizeof(int), 0);
    cudaMemsetAsync(cnt_user, 0, N_USERC * sizeof(int), 0);
    cudaMemsetAsync(tkt, 0, 2 * sizeof(unsigned int), 0);
    cudaMemsetAsync(desc, 0, 2 * 160 * sizeof(unsigned long long), 0);

    // CSR build
    count_kernel<<<(NE + 255) / 256, 256>>>(ui_dst, iu_dst);
    scan_lookback_kernel<<<dim3(98, 2), 256>>>();
    fill_kernel<<<(NE + 255) / 256, 256>>>(ui_src, ui_dst, iu_src, iu_dst);

    // layer 1 aggregation (fused item+user)
    agg_l1_kernel<<<AGG_BLK_ITEM + AGG_BLK_USER, 256>>>(x_user, x_item);

    // layer 1 fused GEMMs (item + user in one launch)
    {
        GemmSide si = { agg_item, W1l_ui, x_item, W1r_ui, b1_ui, h_item, DU, DI, N_ITEMC };
        GemmSide su = { agg_user, W1l_iu, x_user, W1r_iu, b1_iu, h_user, DI, DU, N_USERC };
        gemm_mma_fused<true><<<dim3(MBLK_ITEM + MBLK_USER, 2), 256, GEMM_SMEM>>>(si, su, MBLK_ITEM);
    }

    // layer 2 aggregation (fused)
    agg_l2_kernel<<<AGG_BLK_ITEM + AGG_BLK_USER, 256>>>();

    // layer 2 fused GEMMs
    float* out_user = (float*)d_out;
    float* out_item = out_user + (size_t)N_USERC * HH;
    {
        GemmSide si = { aggH_item, W2l_ui, h_item, W2r_ui, b2_ui, out_item, HH, HH, N_ITEMC };
        GemmSide su = { aggH_user, W2l_iu, h_user, W2r_iu, b2_iu, out_user, HH, HH, N_USERC };
        gemm_mma_fused<false><<<dim3(MBLK_ITEM + MBLK_USER, 2), 256, GEMM_SMEM>>>(si, su, MBLK_ITEM);
    }
}

// round 9
// speedup vs baseline: 3.7127x; 1.7354x over previous
#include <cuda_runtime.h>
#include <cuda_fp16.h>
#include <cstdint>

#define N_USERC 100000
#define N_ITEMC 50000
#define NE      1600000
#define DU      128
#define DI      64
#define HH      256

#define AGG_BLK_ITEM ((N_ITEMC + 7) / 8)     // 6250
#define AGG_BLK_USER ((N_USERC + 7) / 8)     // 12500
#define MBLK_ITEM ((N_ITEMC + 127) / 128)    // 391
#define MBLK_USER ((N_USERC + 127) / 128)    // 782

// ---------------- device scratch ----------------
__device__ int g_cnt_item[N_ITEMC];
__device__ int g_cnt_user[N_USERC];
__device__ int g_cur_item[N_ITEMC];
__device__ int g_cur_user[N_USERC];
__device__ int g_rs_item[N_ITEMC + 1];
__device__ int g_rs_user[N_USERC + 1];
__device__ int g_col_ui[NE];
__device__ int g_col_iu[NE];

__device__ unsigned int g_tkt[2];
__device__ unsigned long long g_desc[2][160];

__device__ __half g_xu_h[(size_t)N_USERC * DU];
__device__ __half g_xi_h[(size_t)N_ITEMC * DI];
__device__ __half g_agg_item_h[(size_t)N_ITEMC * DU];
__device__ __half g_agg_user_h[(size_t)N_USERC * DI];
__device__ __half g_h_item_h[(size_t)N_ITEMC * HH];
__device__ __half g_h_user_h[(size_t)N_USERC * HH];
__device__ __half g_aggH_item_h[(size_t)N_ITEMC * HH];
__device__ __half g_aggH_user_h[(size_t)N_USERC * HH];
__device__ __half g_w_h[360448];

// weight offsets in g_w_h
#define O_W1L_UI 0
#define O_W1R_UI 32768
#define O_W1L_IU 49152
#define O_W1R_IU 65536
#define O_W2L_UI 98304
#define O_W2R_UI 163840
#define O_W2L_IU 229376
#define O_W2R_IU 294912

// ---------------- fp32 -> fp16 convert ----------------
struct CvtSeg { const float* s; __half* d; int n4; };
struct CvtArgs { CvtSeg seg[10]; };

__global__ void cvt_kernel(CvtArgs args) {
#pragma unroll 1
    for (int k = 0; k < 10; k++) {
        CvtSeg g = args.seg[k];
        for (int i = blockIdx.x * blockDim.x + threadIdx.x; i < g.n4;
             i += gridDim.x * blockDim.x) {
            float4 v = __ldg((const float4*)g.s + i);
            __half2 h0 = __float22half2_rn(make_float2(v.x, v.y));
            __half2 h1 = __float22half2_rn(make_float2(v.z, v.w));
            uint2 o;
            o.x = *(uint32_t*)&h0;
            o.y = *(uint32_t*)&h1;
            ((uint2*)g.d)[i] = o;
        }
    }
}

// ---------------- CSR build ----------------
__global__ void count_kernel(const int* __restrict__ ui_dst, const int* __restrict__ iu_dst) {
    int i = blockIdx.x * blockDim.x + threadIdx.x;
    if (i < NE) {
        atomicAdd(&g_cnt_item[ui_dst[i]], 1);
        atomicAdd(&g_cnt_user[iu_dst[i]], 1);
    }
}

__global__ void scan_lookback_kernel() {
    const int y = blockIdx.y;
    const int* __restrict__ cnt = y == 0 ? g_cnt_item : g_cnt_user;
    int* __restrict__ rs  = y == 0 ? g_rs_item  : g_rs_user;
    int* __restrict__ cur = y == 0 ? g_cur_item : g_cur_user;
    const int n = y == 0 ? N_ITEMC : N_USERC;
    const int nblk = (n + 1023) / 1024;
    if (blockIdx.x >= nblk) return;

    __shared__ int s_vb;
    __shared__ int s_wsum[8];
    __shared__ int s_run;
    const int tid = threadIdx.x, lane = tid & 31, wid = tid >> 5;

    if (tid == 0) s_vb = atomicAdd(&g_tkt[y], 1u);
    __syncthreads();
    const int vb = s_vb;
    const int base = vb * 1024 + tid * 4;

    int v0 = 0, v1 = 0, v2 = 0, v3 = 0;
    if (base + 3 < n) {
        v0 = cnt[base]; v1 = cnt[base + 1]; v2 = cnt[base + 2]; v3 = cnt[base + 3];
    } else {
        if (base     < n) v0 = cnt[base];
        if (base + 1 < n) v1 = cnt[base + 1];
        if (base + 2 < n) v2 = cnt[base + 2];
        if (base + 3 < n) v3 = cnt[base + 3];
    }
    const int tot = v0 + v1 + v2 + v3;
    int inc = tot;
#pragma unroll
    for (int o = 1; o < 32; o <<= 1) {
        int u = __shfl_up_sync(0xffffffffu, inc, o);
        if (lane >= o) inc += u;
    }
    if (lane == 31) s_wsum[wid] = inc;
    __syncthreads();
    if (wid == 0) {
        int w = (lane < 8) ? s_wsum[lane] : 0;
#pragma unroll
        for (int o = 1; o < 8; o <<= 1) {
            int u = __shfl_up_sync(0xffffffffu, w, o);
            if (lane >= o) w += u;
        }
        if (lane < 8) s_wsum[lane] = w;
    }
    __syncthreads();
    const int agg = s_wsum[7];
    const int thr_exc = (wid ? s_wsum[wid - 1] : 0) + inc - tot;

    if (tid == 0) {
        if (vb == 0) {
            atomicExch(&g_desc[y][0], (2ull << 32) | (unsigned)agg);
            s_run = 0;
        } else {
            atomicExch(&g_desc[y][vb], (1ull << 32) | (unsigned)agg);
            int run = 0, p = vb - 1;
            while (true) {
                unsigned long long d;
                do { d = atomicAdd(&g_desc[y][p], 0ull); } while ((d >> 32) == 0ull);
                run += (int)(d & 0xffffffffull);
                if ((d >> 32) == 2ull) break;
                p--;
            }
            atomicExch(&g_desc[y][vb], (2ull << 32) | (unsigned)(run + agg));
            s_run = run;
        }
    }
    __syncthreads();
    const int run = s_run;
    const int e0 = run + thr_exc;
    if (base     < n) { rs[base]     = e0;                cur[base]     = 0; }
    if (base + 1 < n) { rs[base + 1] = e0 + v0;           cur[base + 1] = 0; }
    if (base + 2 < n) { rs[base + 2] = e0 + v0 + v1;      cur[base + 2] = 0; }
    if (base + 3 < n) { rs[base + 3] = e0 + v0 + v1 + v2; cur[base + 3] = 0; }
    if (vb == nblk - 1 && tid == 0) rs[n] = run + agg;
}

__global__ void fill_kernel(const int* __restrict__ ui_src, const int* __restrict__ ui_dst,
                            const int* __restrict__ iu_src, const int* __restrict__ iu_dst) {
    int i = blockIdx.x * blockDim.x + threadIdx.x;
    if (i >= NE) return;
    {
        int d = ui_dst[i];
        int p = atomicAdd(&g_cur_item[d], 1);
        g_col_ui[g_rs_item[d] + p] = ui_src[i];
    }
    {
        int d = iu_dst[i];
        int p = atomicAdd(&g_cur_user[d], 1);
        g_col_iu[g_rs_user[d] + p] = iu_src[i];
    }
}

// ---------------- fp16 gather-based segment mean ----------------
// HV = half2 words per lane: 1 (F=64), 2 (F=128), 4 (F=256)
template <int HV>
__device__ __forceinline__ void ld_row(const __half* p, int lane, uint32_t* raw) {
    if constexpr (HV == 4) {
        uint4 t = __ldg((const uint4*)p + lane);
        raw[0] = t.x; raw[1] = t.y; raw[2] = t.z; raw[3] = t.w;
    } else if constexpr (HV == 2) {
        uint2 t = __ldg((const uint2*)p + lane);
        raw[0] = t.x; raw[1] = t.y;
    } else {
        raw[0] = __ldg((const uint32_t*)p + lane);
    }
}

template <int HV>
__device__ __forceinline__ void agg_body_h(const __half* __restrict__ X,
                                           const int* __restrict__ rs,
                                           const int* __restrict__ col,
                                           __half* __restrict__ out, int w, int lane) {
    const int F = HV * 64;
    int s = rs[w], e = rs[w + 1];
    float2 acc[4][HV];
#pragma unroll
    for (int u = 0; u < 4; u++)
#pragma unroll
        for (int v = 0; v < HV; v++) acc[u][v] = make_float2(0.f, 0.f);

    int j = s;
    for (; j + 3 < e; j += 4) {
        uint32_t raw[4][HV];
#pragma unroll
        for (int u = 0; u < 4; u++)
            ld_row<HV>(X + (size_t)col[j + u] * F, lane, raw[u]);
#pragma unroll
        for (int u = 0; u < 4; u++)
#pragma unroll
            for (int v = 0; v < HV; v++) {
                float2 f = __half22float2(*(__half2*)&raw[u][v]);
                acc[u][v].x += f.x; acc[u][v].y += f.y;
            }
    }
    for (; j < e; j++) {
        uint32_t raw[HV];
        ld_row<HV>(X + (size_t)col[j] * F, lane, raw);
#pragma unroll
        for (int v = 0; v < HV; v++) {
            float2 f = __half22float2(*(__half2*)&raw[v]);
            acc[0][v].x += f.x; acc[0][v].y += f.y;
        }
    }
    float inv = (e > s) ? 1.0f / (float)(e - s) : 0.0f;
    uint32_t o[HV];
#pragma unroll
    for (int v = 0; v < HV; v++) {
        float2 m;
        m.x = (acc[0][v].x + acc[1][v].x + acc[2][v].x + acc[3][v].x) * inv;
        m.y = (acc[0][v].y + acc[1][v].y + acc[2][v].y + acc[3][v].y) * inv;
        __half2 h = __float22half2_rn(m);
        o[v] = *(uint32_t*)&h;
    }
    __half* orow = out + (size_t)w * F;
    if constexpr (HV == 4) ((uint4*)orow)[lane] = make_uint4(o[0], o[1], o[2], o[3]);
    else if constexpr (HV == 2) ((uint2*)orow)[lane] = make_uint2(o[0], o[1]);
    else ((uint32_t*)orow)[lane] = o[0];
}

__global__ __launch_bounds__(256) void agg_l1_kernel() {
    const int gb = blockIdx.x;
    const int lane = threadIdx.x & 31;
    const int wl = threadIdx.x >> 5;
    if (gb < AGG_BLK_ITEM) {
        int w = gb * 8 + wl;
        if (w < N_ITEMC) agg_body_h<2>(g_xu_h, g_rs_item, g_col_ui, g_agg_item_h, w, lane);
    } else {
        int w = (gb - AGG_BLK_ITEM) * 8 + wl;
        if (w < N_USERC) agg_body_h<1>(g_xi_h, g_rs_user, g_col_iu, g_agg_user_h, w, lane);
    }
}

__global__ __launch_bounds__(256) void agg_l2_kernel() {
    const int gb = blockIdx.x;
    const int lane = threadIdx.x & 31;
    const int wl = threadIdx.x >> 5;
    if (gb < AGG_BLK_ITEM) {
        int w = gb * 8 + wl;
        if (w < N_ITEMC) agg_body_h<4>(g_h_user_h, g_rs_item, g_col_ui, g_aggH_item_h, w, lane);
    } else {
        int w = (gb - AGG_BLK_ITEM) * 8 + wl;
        if (w < N_USERC) agg_body_h<4>(g_h_item_h, g_rs_user, g_col_iu, g_aggH_user_h, w, lane);
    }
}

// ================= fp16 mma.sync dual-A GEMM (fused item+user) =================
// C[M,256] = act(A1 @ W1^T + A2 @ W2^T + b); A,W fp16, accum fp32.
// CTA 128x128 (grid.y=2), BK=32, 8 warps (2x4), warp 64x32, mma m16n8k16.
// SMEM tiles: 128 rows x 32 halfs, 80B row stride (16B-aligned; LDSM banks
// 20*r mod 32 over 8 rows = all distinct -> conflict-free).
#define HROW_B    80
#define HSTAGE_A  (128 * HROW_B)           // 10240
#define HSTAGE    (2 * HSTAGE_A)           // 20480
#define HGEMM_SMEM (2 * HSTAGE)            // 40960

struct GemmSideH {
    const __half *A1, *W1, *A2, *W2;
    const float* bias;
    void* C;
    int K1, K2, M;
};

__device__ __forceinline__ uint32_t smem_u32(const void* p) {
    uint32_t a;
    asm("{ .reg .u64 t; cvta.to.shared.u64 t, %1; cvt.u32.u64 %0, t; }" : "=r"(a) : "l"(p));
    return a;
}

__device__ __forceinline__ void ldsm_x4(uint32_t* r, uint32_t addr) {
    asm volatile("ldmatrix.sync.aligned.m8n8.x4.shared.b16 {%0,%1,%2,%3}, [%4];"
                 : "=r"(r[0]), "=r"(r[1]), "=r"(r[2]), "=r"(r[3]) : "r"(addr));
}

__device__ __forceinline__ void mma_f16(float* d, const uint32_t* a, uint32_t b0, uint32_t b1) {
    asm volatile(
        "mma.sync.aligned.m16n8k16.row.col.f32.f16.f16.f32 "
        "{%0,%1,%2,%3}, {%4,%5,%6,%7}, {%8,%9}, {%0,%1,%2,%3};"
        : "+f"(d[0]), "+f"(d[1]), "+f"(d[2]), "+f"(d[3])
        : "r"(a[0]), "r"(a[1]), "r"(a[2]), "r"(a[3]), "r"(b0), "r"(b1));
}

__device__ __forceinline__ void sts128(uint32_t addr, uint4 v) {
    asm volatile("st.shared.v4.b32 [%0], {%1,%2,%3,%4};"
                 :: "r"(addr), "r"(v.x), "r"(v.y), "r"(v.z), "r"(v.w) : "memory");
}

template <bool RELU, typename CT>
__global__ __launch_bounds__(256, 2) void gemm_h_fused(GemmSideH sa, GemmSideH sb, int mblk_a) {
    extern __shared__ __align__(16) char dsmem[];
    const uint32_t sm0 = smem_u32(dsmem);

    const bool sideA = (int)blockIdx.x < mblk_a;
    const __half* A1 = sideA ? sa.A1 : sb.A1;
    const __half* W1 = sideA ? sa.W1 : sb.W1;
    const __half* A2 = sideA ? sa.A2 : sb.A2;
    const __half* W2 = sideA ? sa.W2 : sb.W2;
    const float* bias = sideA ? sa.bias : sb.bias;
    CT* C = (CT*)(sideA ? sa.C : sb.C);
    const int K1 = sideA ? sa.K1 : sb.K1;
    const int K2 = sideA ? sa.K2 : sb.K2;
    const int M  = sideA ? sa.M  : sb.M;
    const int mb = sideA ? blockIdx.x : blockIdx.x - mblk_a;

    const int tid = threadIdx.x;
    const int wid = tid >> 5;
    const int lane = tid & 31;
    const int warp_m = wid >> 2;
    const int warp_n = wid & 3;
    const int m0 = mb * 128;
    const int n0 = blockIdx.y * 128;

    const int row0 = tid >> 2;          // 0..63
    const int cc8 = (tid & 3) * 8;      // half offset within BK
    const uint32_t stoff = (uint32_t)(row0 * HROW_B + (tid & 3) * 16);

    float acc[4][4][4];
#pragma unroll
    for (int i = 0; i < 4; i++)
#pragma unroll
        for (int j = 0; j < 4; j++)
#pragma unroll
            for (int k = 0; k < 4; k++) acc[i][j][k] = 0.f;

    const int n1 = K1 / 32;
    const int n2 = K2 / 32;
    const int T = n1 + n2;

    uint4 aR[2], bR[2];

    auto load_g = [&](int it) {
        const __half* A; const __half* W; int K, k0;
        if (it < n1) { A = A1; W = W1; K = K1; k0 = it * 32; }
        else         { A = A2; W = W2; K = K2; k0 = (it - n1) * 32; }
        const int cc = k0 + cc8;
#pragma unroll
        for (int q = 0; q < 2; q++) {
            const int r = row0 + 64 * q;
            aR[q] = (m0 + r < M)
                  ? *(const uint4*)(A + (size_t)(m0 + r) * K + cc)
                  : make_uint4(0u, 0u, 0u, 0u);
            bR[q] = *(const uint4*)(W + (size_t)(n0 + r) * K + cc);
        }
    };

    auto store_s = [&](int st) {
        const uint32_t bA = sm0 + st * HSTAGE;
        const uint32_t bB = bA + HSTAGE_A;
#pragma unroll
        for (int q = 0; q < 2; q++) {
            sts128(bA + stoff + (uint32_t)(64 * q * HROW_B), aR[q]);
            sts128(bB + stoff + (uint32_t)(64 * q * HROW_B), bR[q]);
        }
    };

    const int rowsel = (lane & 7) | (((lane >> 3) & 1) << 3);
    const int colsel = (lane >> 4) * 16;   // byte offset: second 8-col group

    auto compute_s = [&](int st) {
        const uint32_t bA = sm0 + st * HSTAGE;
        const uint32_t bB = bA + HSTAGE_A;
        const uint32_t aBase = bA + (uint32_t)((warp_m * 64 + rowsel) * HROW_B + colsel);
        const uint32_t bBase = bB + (uint32_t)((warp_n * 32 + rowsel) * HROW_B + colsel);
#pragma unroll
        for (int ks = 0; ks < 2; ks++) {
            const uint32_t ko = ks * 32;   // 16 halfs = 32 bytes
            uint32_t af[4][4], bf[8];
#pragma unroll
            for (int i = 0; i < 4; i++)
                ldsm_x4(af[i], aBase + i * (16 * HROW_B) + ko);
            ldsm_x4(bf + 0, bBase + ko);
            ldsm_x4(bf + 4, bBase + 16 * HROW_B + ko);
#pragma unroll
            for (int i = 0; i < 4; i++)
#pragma unroll
                for (int j = 0; j < 4; j++) {
                    const int bi = (j >> 1) * 4 + (j & 1);
                    mma_f16(acc[i][j], af[i], bf[bi], bf[bi + 2]);
                }
        }
    };

    load_g(0);
    store_s(0);
    __syncthreads();
    int s = 0;
#pragma unroll 1
    for (int it = 0; it < T; it++) {
        if (it + 1 < T) load_g(it + 1);
        compute_s(s);
        if (it + 1 < T) store_s(1 - s);
        __syncthreads();
        s ^= 1;
    }

    // epilogue: bias (+relu); CT = __half (h buffers) or float (d_out)
    const int g = lane >> 2;
    const int t = lane & 3;
#pragma unroll
    for (int j = 0; j < 4; j++) {
        const int nb = n0 + warp_n * 32 + j * 8 + t * 2;
        const float bx = bias[nb], by = bias[nb + 1];
#pragma unroll
        for (int i = 0; i < 4; i++) {
            const int rlo = m0 + warp_m * 64 + i * 16 + g;
            if (rlo < M) {
                float vx = acc[i][j][0] + bx, vy = acc[i][j][1] + by;
                if (RELU) { vx = fmaxf(vx, 0.f); vy = fmaxf(vy, 0.f); }
                if constexpr (sizeof(CT) == 2) {
                    __half2 hv = __float22half2_rn(make_float2(vx, vy));
                    *(__half2*)((__half*)C + (size_t)rlo * HH + nb) = hv;
                } else {
                    *(float2*)((float*)C + (size_t)rlo * HH + nb) = make_float2(vx, vy);
                }
            }
            const int rhi = rlo + 8;
            if (rhi < M) {
                float vx = acc[i][j][2] + bx, vy = acc[i][j][3] + by;
                if (RELU) { vx = fmaxf(vx, 0.f); vy = fmaxf(vy, 0.f); }
                if constexpr (sizeof(CT) == 2) {
                    __half2 hv = __float22half2_rn(make_float2(vx, vy));
                    *(__half2*)((__half*)C + (size_t)rhi * HH + nb) = hv;
                } else {
                    *(float2*)((float*)C + (size_t)rhi * HH + nb) = make_float2(vx, vy);
                }
            }
        }
    }
}

// ---------------- host ----------------
extern "C" void kernel_launch(void* const* d_in, const int* in_sizes, int n_in,
                              void* d_out, int out_size) {
    const float* x_user = (const float*)d_in[0];
    const float* x_item = (const float*)d_in[1];
    const int* ui_src = (const int*)d_in[2];
    const int* ui_dst = (const int*)d_in[3];
    const int* iu_src = (const int*)d_in[4];
    const int* iu_dst = (const int*)d_in[5];
    const float* W1l_ui = (const float*)d_in[6];
    const float* b1_ui  = (const float*)d_in[7];
    const float* W1r_ui = (const float*)d_in[8];
    const float* W1l_iu = (const float*)d_in[9];
    const float* b1_iu  = (const float*)d_in[10];
    const float* W1r_iu = (const float*)d_in[11];
    const float* W2l_ui = (const float*)d_in[12];
    const float* b2_ui  = (const float*)d_in[13];
    const float* W2r_ui = (const float*)d_in[14];
    const float* W2l_iu = (const float*)d_in[15];
    const float* b2_iu  = (const float*)d_in[16];
    const float* W2r_iu = (const float*)d_in[17];

    int *cnt_item, *cnt_user;
    unsigned int* tkt;
    unsigned long long* desc;
    __half *xu_h, *xi_h, *agg_item_h, *agg_user_h, *h_item_h, *h_user_h,
           *aggH_item_h, *aggH_user_h, *w_h;
    cudaGetSymbolAddress((void**)&cnt_item, g_cnt_item);
    cudaGetSymbolAddress((void**)&cnt_user, g_cnt_user);
    cudaGetSymbolAddress((void**)&tkt, g_tkt);
    cudaGetSymbolAddress((void**)&desc, g_desc);
    cudaGetSymbolAddress((void**)&xu_h, g_xu_h);
    cudaGetSymbolAddress((void**)&xi_h, g_xi_h);
    cudaGetSymbolAddress((void**)&agg_item_h, g_agg_item_h);
    cudaGetSymbolAddress((void**)&agg_user_h, g_agg_user_h);
    cudaGetSymbolAddress((void**)&h_item_h, g_h_item_h);
    cudaGetSymbolAddress((void**)&h_user_h, g_h_user_h);
    cudaGetSymbolAddress((void**)&aggH_item_h, g_aggH_item_h);
    cudaGetSymbolAddress((void**)&aggH_user_h, g_aggH_user_h);
    cudaGetSymbolAddress((void**)&w_h, g_w_h);

    cudaFuncSetAttribute(gemm_h_fused<true, __half>,
                         cudaFuncAttributeMaxDynamicSharedMemorySize, HGEMM_SMEM);
    cudaFuncSetAttribute(gemm_h_fused<false, float>,
                         cudaFuncAttributeMaxDynamicSharedMemorySize, HGEMM_SMEM);

    cudaMemsetAsync(cnt_item, 0, N_ITEMC * sizeof(int), 0);
    cudaMemsetAsync(cnt_user, 0, N_USERC * sizeof(int), 0);
    cudaMemsetAsync(tkt, 0, 2 * sizeof(unsigned int), 0);
    cudaMemsetAsync(desc, 0, 2 * 160 * sizeof(unsigned long long), 0);

    // fp32 -> fp16 pre-convert (features + weights)
    {
        CvtArgs a;
        a.seg[0] = { x_user, xu_h, (N_USERC * DU) / 4 };
        a.seg[1] = { x_item, xi_h, (N_ITEMC * DI) / 4 };
        a.seg[2] = { W1l_ui, w_h + O_W1L_UI, (HH * DU) / 4 };
        a.seg[3] = { W1r_ui, w_h + O_W1R_UI, (HH * DI) / 4 };
        a.seg[4] = { W1l_iu, w_h + O_W1L_IU, (HH * DI) / 4 };
        a.seg[5] = { W1r_iu, w_h + O_W1R_IU, (HH * DU) / 4 };
        a.seg[6] = { W2l_ui, w_h + O_W2L_UI, (HH * HH) / 4 };
        a.seg[7] = { W2r_ui, w_h + O_W2R_UI, (HH * HH) / 4 };
        a.seg[8] = { W2l_iu, w_h + O_W2L_IU, (HH * HH) / 4 };
        a.seg[9] = { W2r_iu, w_h + O_W2R_IU, (HH * HH) / 4 };
        cvt_kernel<<<1024, 256>>>(a);
    }

    // CSR build
    count_kernel<<<(NE + 255) / 256, 256>>>(ui_dst, iu_dst);
    scan_lookback_kernel<<<dim3(98, 2), 256>>>();
    fill_kernel<<<(NE + 255) / 256, 256>>>(ui_src, ui_dst, iu_src, iu_dst);

    // layer 1 aggregation (fp16 features, fp32 accumulate)
    agg_l1_kernel<<<AGG_BLK_ITEM + AGG_BLK_USER, 256>>>();

    // layer 1 fused GEMMs (fp16 in, fp16 out + relu)
    {
        GemmSideH si = { agg_item_h, w_h + O_W1L_UI, xi_h, w_h + O_W1R_UI,
                         b1_ui, h_item_h, DU, DI, N_ITEMC };
        GemmSideH su = { agg_user_h, w_h + O_W1L_IU, xu_h, w_h + O_W1R_IU,
                         b1_iu, h_user_h, DI, DU, N_USERC };
        gemm_h_fused<true, __half><<<dim3(MBLK_ITEM + MBLK_USER, 2), 256, HGEMM_SMEM>>>(
            si, su, MBLK_ITEM);
    }

    // layer 2 aggregation
    agg_l2_kernel<<<AGG_BLK_ITEM + AGG_BLK_USER, 256>>>();

    // layer 2 fused GEMMs (fp16 in, fp32 out)
    float* out_user = (float*)d_out;
    float* out_item = out_user + (size_t)N_USERC * HH;
    {
        GemmSideH si = { aggH_item_h, w_h + O_W2L_UI, h_item_h, w_h + O_W2R_UI,
                         b2_ui, out_item, HH, HH, N_ITEMC };
        GemmSideH su = { aggH_user_h, w_h + O_W2L_IU, h_user_h, w_h + O_W2R_IU,
                         b2_iu, out_user, HH, HH, N_USERC };
        gemm_h_fused<false, float><<<dim3(MBLK_ITEM + MBLK_USER, 2), 256, HGEMM_SMEM>>>(
            si, su, MBLK_ITEM);
    }
}

// round 10
// speedup vs baseline: 3.8203x; 1.0290x over previous
#include <cuda_runtime.h>
#include <cuda_fp16.h>
#include <cstdint>

#define N_USERC 100000
#define N_ITEMC 50000
#define NE      1600000
#define DU      128
#define DI      64
#define HH      256

#define AGG_BLK_ITEM ((N_ITEMC + 7) / 8)     // 6250
#define AGG_BLK_USER ((N_USERC + 7) / 8)     // 12500
#define MBLK_ITEM ((N_ITEMC + 127) / 128)    // 391
#define MBLK_USER ((N_USERC + 127) / 128)    // 782

// ---------------- device scratch ----------------
__device__ __align__(16) int g_cnt_item[N_ITEMC];
__device__ __align__(16) int g_cnt_user[N_USERC];
__device__ __align__(16) int g_cur_item[N_ITEMC];
__device__ __align__(16) int g_cur_user[N_USERC];
__device__ __align__(16) int g_rs_item[N_ITEMC + 1];
__device__ __align__(16) int g_rs_user[N_USERC + 1];
__device__ __align__(16) int g_col_ui[NE];
__device__ __align__(16) int g_col_iu[NE];

__device__ unsigned int g_tkt[2];
__device__ __align__(16) unsigned long long g_desc[2][160];

__device__ __align__(128) __half g_xu_h[(size_t)N_USERC * DU];
__device__ __align__(128) __half g_xi_h[(size_t)N_ITEMC * DI];
__device__ __align__(128) __half g_agg_item_h[(size_t)N_ITEMC * DU];
__device__ __align__(128) __half g_agg_user_h[(size_t)N_USERC * DI];
__device__ __align__(128) __half g_h_item_h[(size_t)N_ITEMC * HH];
__device__ __align__(128) __half g_h_user_h[(size_t)N_USERC * HH];
__device__ __align__(128) __half g_aggH_item_h[(size_t)N_ITEMC * HH];
__device__ __align__(128) __half g_aggH_user_h[(size_t)N_USERC * HH];
__device__ __align__(128) __half g_w_h[360448];

// weight offsets in g_w_h
#define O_W1L_UI 0
#define O_W1R_UI 32768
#define O_W1L_IU 49152
#define O_W1R_IU 65536
#define O_W2L_UI 98304
#define O_W2R_UI 163840
#define O_W2L_IU 229376
#define O_W2R_IU 294912

// ---------------- fp32 -> fp16 convert + scratch zeroing ----------------
struct CvtSeg { const float* s; __half* d; int n4; };
struct CvtArgs { CvtSeg seg[10]; };

__global__ void cvt_kernel(CvtArgs args) {
    const int gid = blockIdx.x * blockDim.x + threadIdx.x;
    const int stride = gridDim.x * blockDim.x;
#pragma unroll 1
    for (int k = 0; k < 10; k++) {
        CvtSeg g = args.seg[k];
        for (int i = gid; i < g.n4; i += stride) {
            float4 v = __ldg((const float4*)g.s + i);
            __half2 h0 = __float22half2_rn(make_float2(v.x, v.y));
            __half2 h1 = __float22half2_rn(make_float2(v.z, v.w));
            uint2 o;
            o.x = *(uint32_t*)&h0;
            o.y = *(uint32_t*)&h1;
            ((uint2*)g.d)[i] = o;
        }
    }
    // zero counters / scan state (replaces memsets)
    for (int i = gid; i < N_ITEMC / 4; i += stride) ((int4*)g_cnt_item)[i] = make_int4(0, 0, 0, 0);
    for (int i = gid; i < N_USERC / 4; i += stride) ((int4*)g_cnt_user)[i] = make_int4(0, 0, 0, 0);
    for (int i = gid; i < 320; i += stride) ((unsigned long long*)g_desc)[i] = 0ull;
    if (gid == 0) { g_tkt[0] = 0u; g_tkt[1] = 0u; }
}

// ---------------- CSR build (4 edges / thread for MLP) ----------------
__global__ void count_kernel(const int* __restrict__ ui_dst, const int* __restrict__ iu_dst) {
    int i = blockIdx.x * blockDim.x + threadIdx.x;
    if (i >= NE / 4) return;
    int4 a = __ldg((const int4*)ui_dst + i);
    int4 b = __ldg((const int4*)iu_dst + i);
    atomicAdd(&g_cnt_item[a.x], 1); atomicAdd(&g_cnt_item[a.y], 1);
    atomicAdd(&g_cnt_item[a.z], 1); atomicAdd(&g_cnt_item[a.w], 1);
    atomicAdd(&g_cnt_user[b.x], 1); atomicAdd(&g_cnt_user[b.y], 1);
    atomicAdd(&g_cnt_user[b.z], 1); atomicAdd(&g_cnt_user[b.w], 1);
}

__global__ void scan_lookback_kernel() {
    const int y = blockIdx.y;
    const int* __restrict__ cnt = y == 0 ? g_cnt_item : g_cnt_user;
    int* __restrict__ rs  = y == 0 ? g_rs_item  : g_rs_user;
    int* __restrict__ cur = y == 0 ? g_cur_item : g_cur_user;
    const int n = y == 0 ? N_ITEMC : N_USERC;
    const int nblk = (n + 1023) / 1024;
    if (blockIdx.x >= nblk) return;

    __shared__ int s_vb;
    __shared__ int s_wsum[8];
    __shared__ int s_run;
    const int tid = threadIdx.x, lane = tid & 31, wid = tid >> 5;

    if (tid == 0) s_vb = atomicAdd(&g_tkt[y], 1u);
    __syncthreads();
    const int vb = s_vb;
    const int base = vb * 1024 + tid * 4;

    int v0 = 0, v1 = 0, v2 = 0, v3 = 0;
    if (base + 3 < n) {
        v0 = cnt[base]; v1 = cnt[base + 1]; v2 = cnt[base + 2]; v3 = cnt[base + 3];
    } else {
        if (base     < n) v0 = cnt[base];
        if (base + 1 < n) v1 = cnt[base + 1];
        if (base + 2 < n) v2 = cnt[base + 2];
        if (base + 3 < n) v3 = cnt[base + 3];
    }
    const int tot = v0 + v1 + v2 + v3;
    int inc = tot;
#pragma unroll
    for (int o = 1; o < 32; o <<= 1) {
        int u = __shfl_up_sync(0xffffffffu, inc, o);
        if (lane >= o) inc += u;
    }
    if (lane == 31) s_wsum[wid] = inc;
    __syncthreads();
    if (wid == 0) {
        int w = (lane < 8) ? s_wsum[lane] : 0;
#pragma unroll
        for (int o = 1; o < 8; o <<= 1) {
            int u = __shfl_up_sync(0xffffffffu, w, o);
            if (lane >= o) w += u;
        }
        if (lane < 8) s_wsum[lane] = w;
    }
    __syncthreads();
    const int agg = s_wsum[7];
    const int thr_exc = (wid ? s_wsum[wid - 1] : 0) + inc - tot;

    if (tid == 0) {
        if (vb == 0) {
            atomicExch(&g_desc[y][0], (2ull << 32) | (unsigned)agg);
            s_run = 0;
        } else {
            atomicExch(&g_desc[y][vb], (1ull << 32) | (unsigned)agg);
            int run = 0, p = vb - 1;
            while (true) {
                unsigned long long d;
                do { d = atomicAdd(&g_desc[y][p], 0ull); } while ((d >> 32) == 0ull);
                run += (int)(d & 0xffffffffull);
                if ((d >> 32) == 2ull) break;
                p--;
            }
            atomicExch(&g_desc[y][vb], (2ull << 32) | (unsigned)(run + agg));
            s_run = run;
        }
    }
    __syncthreads();
    const int run = s_run;
    const int e0 = run + thr_exc;
    if (base     < n) { rs[base]     = e0;                cur[base]     = 0; }
    if (base + 1 < n) { rs[base + 1] = e0 + v0;           cur[base + 1] = 0; }
    if (base + 2 < n) { rs[base + 2] = e0 + v0 + v1;      cur[base + 2] = 0; }
    if (base + 3 < n) { rs[base + 3] = e0 + v0 + v1 + v2; cur[base + 3] = 0; }
    if (vb == nblk - 1 && tid == 0) rs[n] = run + agg;
}

__global__ void fill_kernel(const int* __restrict__ ui_src, const int* __restrict__ ui_dst,
                            const int* __restrict__ iu_src, const int* __restrict__ iu_dst) {
    int i = blockIdx.x * blockDim.x + threadIdx.x;
    if (i >= NE / 4) return;
    int4 us = __ldg((const int4*)ui_src + i);
    int4 ud = __ldg((const int4*)ui_dst + i);
    int4 is = __ldg((const int4*)iu_src + i);
    int4 id = __ldg((const int4*)iu_dst + i);
    {
        int p0 = atomicAdd(&g_cur_item[ud.x], 1);
        int p1 = atomicAdd(&g_cur_item[ud.y], 1);
        int p2 = atomicAdd(&g_cur_item[ud.z], 1);
        int p3 = atomicAdd(&g_cur_item[ud.w], 1);
        g_col_ui[g_rs_item[ud.x] + p0] = us.x;
        g_col_ui[g_rs_item[ud.y] + p1] = us.y;
        g_col_ui[g_rs_item[ud.z] + p2] = us.z;
        g_col_ui[g_rs_item[ud.w] + p3] = us.w;
    }
    {
        int p0 = atomicAdd(&g_cur_user[id.x], 1);
        int p1 = atomicAdd(&g_cur_user[id.y], 1);
        int p2 = atomicAdd(&g_cur_user[id.z], 1);
        int p3 = atomicAdd(&g_cur_user[id.w], 1);
        g_col_iu[g_rs_user[id.x] + p0] = is.x;
        g_col_iu[g_rs_user[id.y] + p1] = is.y;
        g_col_iu[g_rs_user[id.z] + p2] = is.z;
        g_col_iu[g_rs_user[id.w] + p3] = is.w;
    }
}

// ---------------- fp16 gather-based segment mean ----------------
template <int HV>
__device__ __forceinline__ void ld_row(const __half* p, int lane, uint32_t* raw) {
    if constexpr (HV == 4) {
        uint4 t = __ldg((const uint4*)p + lane);
        raw[0] = t.x; raw[1] = t.y; raw[2] = t.z; raw[3] = t.w;
    } else if constexpr (HV == 2) {
        uint2 t = __ldg((const uint2*)p + lane);
        raw[0] = t.x; raw[1] = t.y;
    } else {
        raw[0] = __ldg((const uint32_t*)p + lane);
    }
}

template <int HV>
__device__ __forceinline__ void agg_body_h(const __half* __restrict__ X,
                                           const int* __restrict__ rs,
                                           const int* __restrict__ col,
                                           __half* __restrict__ out, int w, int lane) {
    const int F = HV * 64;
    int s = rs[w], e = rs[w + 1];
    float2 acc[4][HV];
#pragma unroll
    for (int u = 0; u < 4; u++)
#pragma unroll
        for (int v = 0; v < HV; v++) acc[u][v] = make_float2(0.f, 0.f);

    int j = s;
    for (; j + 3 < e; j += 4) {
        uint32_t raw[4][HV];
#pragma unroll
        for (int u = 0; u < 4; u++)
            ld_row<HV>(X + (size_t)col[j + u] * F, lane, raw[u]);
#pragma unroll
        for (int u = 0; u < 4; u++)
#pragma unroll
            for (int v = 0; v < HV; v++) {
                float2 f = __half22float2(*(__half2*)&raw[u][v]);
                acc[u][v].x += f.x; acc[u][v].y += f.y;
            }
    }
    for (; j < e; j++) {
        uint32_t raw[HV];
        ld_row<HV>(X + (size_t)col[j] * F, lane, raw);
#pragma unroll
        for (int v = 0; v < HV; v++) {
            float2 f = __half22float2(*(__half2*)&raw[v]);
            acc[0][v].x += f.x; acc[0][v].y += f.y;
        }
    }
    float inv = (e > s) ? 1.0f / (float)(e - s) : 0.0f;
    uint32_t o[HV];
#pragma unroll
    for (int v = 0; v < HV; v++) {
        float2 m;
        m.x = (acc[0][v].x + acc[1][v].x + acc[2][v].x + acc[3][v].x) * inv;
        m.y = (acc[0][v].y + acc[1][v].y + acc[2][v].y + acc[3][v].y) * inv;
        __half2 h = __float22half2_rn(m);
        o[v] = *(uint32_t*)&h;
    }
    __half* orow = out + (size_t)w * F;
    if constexpr (HV == 4) ((uint4*)orow)[lane] = make_uint4(o[0], o[1], o[2], o[3]);
    else if constexpr (HV == 2) ((uint2*)orow)[lane] = make_uint2(o[0], o[1]);
    else ((uint32_t*)orow)[lane] = o[0];
}

__global__ __launch_bounds__(256) void agg_l1_kernel() {
    const int gb = blockIdx.x;
    const int lane = threadIdx.x & 31;
    const int wl = threadIdx.x >> 5;
    if (gb < AGG_BLK_ITEM) {
        int w = gb * 8 + wl;
        if (w < N_ITEMC) agg_body_h<2>(g_xu_h, g_rs_item, g_col_ui, g_agg_item_h, w, lane);
    } else {
        int w = (gb - AGG_BLK_ITEM) * 8 + wl;
        if (w < N_USERC) agg_body_h<1>(g_xi_h, g_rs_user, g_col_iu, g_agg_user_h, w, lane);
    }
}

__global__ __launch_bounds__(256) void agg_l2_kernel() {
    const int gb = blockIdx.x;
    const int lane = threadIdx.x & 31;
    const int wl = threadIdx.x >> 5;
    if (gb < AGG_BLK_ITEM) {
        int w = gb * 8 + wl;
        if (w < N_ITEMC) agg_body_h<4>(g_h_user_h, g_rs_item, g_col_ui, g_aggH_item_h, w, lane);
    } else {
        int w = (gb - AGG_BLK_ITEM) * 8 + wl;
        if (w < N_USERC) agg_body_h<4>(g_h_item_h, g_rs_user, g_col_iu, g_aggH_user_h, w, lane);
    }
}

// ================= fp16 mma.sync dual-A GEMM, cp.async 3-stage =================
// C[M,256] = act(A1 @ W1^T + A2 @ W2^T + b); A,W fp16, accum fp32.
// CTA 128x128 (grid.y=2), BK=32, 8 warps (2x4), warp 64x32, mma m16n8k16.
// SMEM: 128 rows x 32 halfs, 80B row stride; 3 cp.async stages.
#define HROW_B    80
#define HSTAGE_A  (128 * HROW_B)           // 10240
#define HSTAGE    (2 * HSTAGE_A)           // 20480
#define NSTAGE    3
#define HGEMM_SMEM (NSTAGE * HSTAGE)       // 61440

struct GemmSideH {
    const __half *A1, *W1, *A2, *W2;
    const float* bias;
    void* C;
    int K1, K2, M;
};

__device__ __forceinline__ uint32_t smem_u32(const void* p) {
    uint32_t a;
    asm("{ .reg .u64 t; cvta.to.shared.u64 t, %1; cvt.u32.u64 %0, t; }" : "=r"(a) : "l"(p));
    return a;
}

__device__ __forceinline__ void ldsm_x4(uint32_t* r, uint32_t addr) {
    asm volatile("ldmatrix.sync.aligned.m8n8.x4.shared.b16 {%0,%1,%2,%3}, [%4];"
                 : "=r"(r[0]), "=r"(r[1]), "=r"(r[2]), "=r"(r[3]) : "r"(addr));
}

__device__ __forceinline__ void mma_f16(float* d, const uint32_t* a, uint32_t b0, uint32_t b1) {
    asm volatile(
        "mma.sync.aligned.m16n8k16.row.col.f32.f16.f16.f32 "
        "{%0,%1,%2,%3}, {%4,%5,%6,%7}, {%8,%9}, {%0,%1,%2,%3};"
        : "+f"(d[0]), "+f"(d[1]), "+f"(d[2]), "+f"(d[3])
        : "r"(a[0]), "r"(a[1]), "r"(a[2]), "r"(a[3]), "r"(b0), "r"(b1));
}

__device__ __forceinline__ void cp_async16(uint32_t smem, const void* g, bool pred) {
    int sz = pred ? 16 : 0;
    asm volatile("cp.async.cg.shared.global [%0], [%1], 16, %2;"
                 :: "r"(smem), "l"(g), "r"(sz) : "memory");
}
#define CP_COMMIT() asm volatile("cp.async.commit_group;" ::: "memory")
#define CP_WAIT1()  asm volatile("cp.async.wait_group 1;" ::: "memory")

template <bool RELU, typename CT>
__global__ __launch_bounds__(256, 2) void gemm_h_fused(GemmSideH sa, GemmSideH sb, int mblk_a) {
    extern __shared__ __align__(16) char dsmem[];
    const uint32_t sm0 = smem_u32(dsmem);

    const bool sideA = (int)blockIdx.x < mblk_a;
    const __half* A1 = sideA ? sa.A1 : sb.A1;
    const __half* W1 = sideA ? sa.W1 : sb.W1;
    const __half* A2 = sideA ? sa.A2 : sb.A2;
    const __half* W2 = sideA ? sa.W2 : sb.W2;
    const float* bias = sideA ? sa.bias : sb.bias;
    CT* C = (CT*)(sideA ? sa.C : sb.C);
    const int K1 = sideA ? sa.K1 : sb.K1;
    const int K2 = sideA ? sa.K2 : sb.K2;
    const int M  = sideA ? sa.M  : sb.M;
    const int mb = sideA ? blockIdx.x : blockIdx.x - mblk_a;

    const int tid = threadIdx.x;
    const int wid = tid >> 5;
    const int lane = tid & 31;
    const int warp_m = wid >> 2;
    const int warp_n = wid & 3;
    const int m0 = mb * 128;
    const int n0 = blockIdx.y * 128;

    const int row0 = tid >> 2;          // 0..63
    const int cc8 = (tid & 3) * 8;      // half offset within BK
    const uint32_t stoff = (uint32_t)(row0 * HROW_B + (tid & 3) * 16);

    float acc[4][4][4];
#pragma unroll
    for (int i = 0; i < 4; i++)
#pragma unroll
        for (int j = 0; j < 4; j++)
#pragma unroll
            for (int k = 0; k < 4; k++) acc[i][j][k] = 0.f;

    const int n1 = K1 / 32;
    const int n2 = K2 / 32;
    const int T = n1 + n2;

    // issue cp.async for iteration `it` into stage slot
    auto issue_g = [&](int it, int slot) {
        const __half* A; const __half* W; int K, k0;
        if (it < n1) { A = A1; W = W1; K = K1; k0 = it * 32; }
        else         { A = A2; W = W2; K = K2; k0 = (it - n1) * 32; }
        const int cc = k0 + cc8;
        const uint32_t bA = sm0 + slot * HSTAGE;
        const uint32_t bB = bA + HSTAGE_A;
#pragma unroll
        for (int q = 0; q < 2; q++) {
            const int r = row0 + 64 * q;
            cp_async16(bA + stoff + (uint32_t)(64 * q * HROW_B),
                       A + (size_t)(m0 + r) * K + cc, m0 + r < M);
            cp_async16(bB + stoff + (uint32_t)(64 * q * HROW_B),
                       W + (size_t)(n0 + r) * K + cc, true);
        }
    };

    const int rowsel = (lane & 7) | (((lane >> 3) & 1) << 3);
    const int colsel = (lane >> 4) * 16;

    auto compute_s = [&](int st) {
        const uint32_t bA = sm0 + st * HSTAGE;
        const uint32_t bB = bA + HSTAGE_A;
        const uint32_t aBase = bA + (uint32_t)((warp_m * 64 + rowsel) * HROW_B + colsel);
        const uint32_t bBase = bB + (uint32_t)((warp_n * 32 + rowsel) * HROW_B + colsel);
#pragma unroll
        for (int ks = 0; ks < 2; ks++) {
            const uint32_t ko = ks * 32;
            uint32_t af[4][4], bf[8];
#pragma unroll
            for (int i = 0; i < 4; i++)
                ldsm_x4(af[i], aBase + i * (16 * HROW_B) + ko);
            ldsm_x4(bf + 0, bBase + ko);
            ldsm_x4(bf + 4, bBase + 16 * HROW_B + ko);
#pragma unroll
            for (int i = 0; i < 4; i++)
#pragma unroll
                for (int j = 0; j < 4; j++) {
                    const int bi = (j >> 1) * 4 + (j & 1);
                    mma_f16(acc[i][j], af[i], bf[bi], bf[bi + 2]);
                }
        }
    };

    // prologue: stages 0 and 1 in flight
    issue_g(0, 0);
    CP_COMMIT();
    if (T > 1) issue_g(1, 1);
    CP_COMMIT();
    CP_WAIT1();              // stage 0 ready
    __syncthreads();

    int slot = 0;
#pragma unroll 1
    for (int it = 0; it < T; it++) {
        compute_s(slot);
        if (it + 2 < T) issue_g(it + 2, (it + 2) % NSTAGE);
        CP_COMMIT();
        CP_WAIT1();          // stage it+1 ready
        __syncthreads();     // also: all warps done reading stage `slot`
        slot = (slot + 1 == NSTAGE) ? 0 : slot + 1;
    }

    // epilogue: bias (+relu); CT = __half (h buffers) or float (d_out)
    const int g = lane >> 2;
    const int t = lane & 3;
#pragma unroll
    for (int j = 0; j < 4; j++) {
        const int nb = n0 + warp_n * 32 + j * 8 + t * 2;
        const float bx = bias[nb], by = bias[nb + 1];
#pragma unroll
        for (int i = 0; i < 4; i++) {
            const int rlo = m0 + warp_m * 64 + i * 16 + g;
            if (rlo < M) {
                float vx = acc[i][j][0] + bx, vy = acc[i][j][1] + by;
                if (RELU) { vx = fmaxf(vx, 0.f); vy = fmaxf(vy, 0.f); }
                if constexpr (sizeof(CT) == 2) {
                    __half2 hv = __float22half2_rn(make_float2(vx, vy));
                    *(__half2*)((__half*)C + (size_t)rlo * HH + nb) = hv;
                } else {
                    *(float2*)((float*)C + (size_t)rlo * HH + nb) = make_float2(vx, vy);
                }
            }
            const int rhi = rlo + 8;
            if (rhi < M) {
                float vx = acc[i][j][2] + bx, vy = acc[i][j][3] + by;
                if (RELU) { vx = fmaxf(vx, 0.f); vy = fmaxf(vy, 0.f); }
                if constexpr (sizeof(CT) == 2) {
                    __half2 hv = __float22half2_rn(make_float2(vx, vy));
                    *(__half2*)((__half*)C + (size_t)rhi * HH + nb) = hv;
                } else {
                    *(float2*)((float*)C + (size_t)rhi * HH + nb) = make_float2(vx, vy);
                }
            }
        }
    }
}

// ---------------- host ----------------
extern "C" void kernel_launch(void* const* d_in, const int* in_sizes, int n_in,
                              void* d_out, int out_size) {
    const float* x_user = (const float*)d_in[0];
    const float* x_item = (const float*)d_in[1];
    const int* ui_src = (const int*)d_in[2];
    const int* ui_dst = (const int*)d_in[3];
    const int* iu_src = (const int*)d_in[4];
    const int* iu_dst = (const int*)d_in[5];
    const float* W1l_ui = (const float*)d_in[6];
    const float* b1_ui  = (const float*)d_in[7];
    const float* W1r_ui = (const float*)d_in[8];
    const float* W1l_iu = (const float*)d_in[9];
    const float* b1_iu  = (const float*)d_in[10];
    const float* W1r_iu = (const float*)d_in[11];
    const float* W2l_ui = (const float*)d_in[12];
    const float* b2_ui  = (const float*)d_in[13];
    const float* W2r_ui = (const float*)d_in[14];
    const float* W2l_iu = (const float*)d_in[15];
    const float* b2_iu  = (const float*)d_in[16];
    const float* W2r_iu = (const float*)d_in[17];

    __half *xu_h, *xi_h, *agg_item_h, *agg_user_h, *h_item_h, *h_user_h,
           *aggH_item_h, *aggH_user_h, *w_h;
    cudaGetSymbolAddress((void**)&xu_h, g_xu_h);
    cudaGetSymbolAddress((void**)&xi_h, g_xi_h);
    cudaGetSymbolAddress((void**)&agg_item_h, g_agg_item_h);
    cudaGetSymbolAddress((void**)&agg_user_h, g_agg_user_h);
    cudaGetSymbolAddress((void**)&h_item_h, g_h_item_h);
    cudaGetSymbolAddress((void**)&h_user_h, g_h_user_h);
    cudaGetSymbolAddress((void**)&aggH_item_h, g_aggH_item_h);
    cudaGetSymbolAddress((void**)&aggH_user_h, g_aggH_user_h);
    cudaGetSymbolAddress((void**)&w_h, g_w_h);

    cudaFuncSetAttribute(gemm_h_fused<true, __half>,
                         cudaFuncAttributeMaxDynamicSharedMemorySize, HGEMM_SMEM);
    cudaFuncSetAttribute(gemm_h_fused<false, float>,
                         cudaFuncAttributeMaxDynamicSharedMemorySize, HGEMM_SMEM);

    // fp32 -> fp16 pre-convert (features + weights) + scratch zeroing
    {
        CvtArgs a;
        a.seg[0] = { x_user, xu_h, (N_USERC * DU) / 4 };
        a.seg[1] = { x_item, xi_h, (N_ITEMC * DI) / 4 };
        a.seg[2] = { W1l_ui, w_h + O_W1L_UI, (HH * DU) / 4 };
        a.seg[3] = { W1r_ui, w_h + O_W1R_UI, (HH * DI) / 4 };
        a.seg[4] = { W1l_iu, w_h + O_W1L_IU, (HH * DI) / 4 };
        a.seg[5] = { W1r_iu, w_h + O_W1R_IU, (HH * DU) / 4 };
        a.seg[6] = { W2l_ui, w_h + O_W2L_UI, (HH * HH) / 4 };
        a.seg[7] = { W2r_ui, w_h + O_W2R_UI, (HH * HH) / 4 };
        a.seg[8] = { W2l_iu, w_h + O_W2L_IU, (HH * HH) / 4 };
        a.seg[9] = { W2r_iu, w_h + O_W2R_IU, (HH * HH) / 4 };
        cvt_kernel<<<1024, 256>>>(a);
    }

    // CSR build (4 edges per thread)
    count_kernel<<<(NE / 4 + 255) / 256, 256>>>(ui_dst, iu_dst);
    scan_lookback_kernel<<<dim3(98, 2), 256>>>();
    fill_kernel<<<(NE / 4 + 255) / 256, 256>>>(ui_src, ui_dst, iu_src, iu_dst);

    // layer 1 aggregation (fp16 features, fp32 accumulate)
    agg_l1_kernel<<<AGG_BLK_ITEM + AGG_BLK_USER, 256>>>();

    // layer 1 fused GEMMs (fp16 in, fp16 out + relu)
    {
        GemmSideH si = { agg_item_h, w_h + O_W1L_UI, xi_h, w_h + O_W1R_UI,
                         b1_ui, h_item_h, DU, DI, N_ITEMC };
        GemmSideH su = { agg_user_h, w_h + O_W1L_IU, xu_h, w_h + O_W1R_IU,
                         b1_iu, h_user_h, DI, DU, N_USERC };
        gemm_h_fused<true, __half><<<dim3(MBLK_ITEM + MBLK_USER, 2), 256, HGEMM_SMEM>>>(
            si, su, MBLK_ITEM);
    }

    // layer 2 aggregation
    agg_l2_kernel<<<AGG_BLK_ITEM + AGG_BLK_USER, 256>>>();

    // layer 2 fused GEMMs (fp16 in, fp32 out)
    float* out_user = (float*)d_out;
    float* out_item = out_user + (size_t)N_USERC * HH;
    {
        GemmSideH si = { aggH_item_h, w_h + O_W2L_UI, h_item_h, w_h + O_W2R_UI,
                         b2_ui, out_item, HH, HH, N_ITEMC };
        GemmSideH su = { aggH_user_h, w_h + O_W2L_IU, h_user_h, w_h + O_W2R_IU,
                         b2_iu, out_user, HH, HH, N_USERC };
        gemm_h_fused<false, float><<<dim3(MBLK_ITEM + MBLK_USER, 2), 256, HGEMM_SMEM>>>(
            si, su, MBLK_ITEM);
    }
}